// round 7
// baseline (speedup 1.0000x reference)
#include <cuda_runtime.h>
#include <cuda_fp16.h>
#include <math_constants.h>
#include <cstdint>

// ---------------- problem constants ----------------
#define NN 16384      // nodes
#define GG 256        // graphs
#define NPG 64        // nodes per graph
#define FF 64         // per-head features
#define DD 512        // H*F
#define NTOT 1024     // fused Wl|Wr output width
#define EMAX 147456

// ---------------- scratch ----------------
__device__ __half g_XLRh[NN * NTOT];    // fused xl|xr GEMM output (fp16)
__device__ float  g_A [NN * DD];        // agg output
__device__ float  g_B [NN * FF];        // layer-3 norm output
__device__ __half g_Xh[NN * 256];       // fp16 input x
__device__ __half g_Bh[NN * DD];        // fp16 norm outputs
__device__ __half g_Wh[1310720];        // fp16 transposed weights [1024][K] x 3
__device__ int    g_cnt [NN];
__device__ int    g_row [NN + 1];
__device__ int    g_fill[NN];
__device__ int    g_csrc[EMAX];

// ---------------- helpers ----------------
__device__ __forceinline__ uint32_t smem_u32(const void* p) {
    return (uint32_t)__cvta_generic_to_shared(p);
}
__device__ __forceinline__ void cp16(uint32_t d, const void* s) {
    asm volatile("cp.async.cg.shared.global [%0], [%1], 16;" :: "r"(d), "l"(s));
}

// ---------------- prep kernels ----------------
__global__ void to_half_kernel(const float4* __restrict__ in, __half2* __restrict__ out, int n4) {
    int i = blockIdx.x * blockDim.x + threadIdx.x;
    if (i < n4) {
        float4 v = in[i];
        out[i * 2]     = __floats2half2_rn(v.x, v.y);
        out[i * 2 + 1] = __floats2half2_rn(v.z, v.w);
    }
}

__global__ void transpose_half_kernel(const float* __restrict__ W, __half* __restrict__ Wt, int K) {
    __shared__ float t[32][33];
    int bx = blockIdx.x * 32;
    int by = blockIdx.y * 32;
    int x = threadIdx.x, y = threadIdx.y;
#pragma unroll
    for (int j = 0; j < 32; j += 8) t[y + j][x] = W[(size_t)(by + y + j) * DD + bx + x];
    __syncthreads();
#pragma unroll
    for (int j = 0; j < 32; j += 8)
        Wt[(size_t)(bx + y + j) * K + by + x] = __float2half_rn(t[x][y + j]);
}

// ---------------- CSR build ----------------
__global__ void zero_int_kernel(int* p, int n) {
    int i = blockIdx.x * blockDim.x + threadIdx.x;
    if (i < n) p[i] = 0;
}
__global__ void count_kernel(const int* __restrict__ dst, int E, int* __restrict__ cnt) {
    int e = blockIdx.x * blockDim.x + threadIdx.x;
    if (e < E) atomicAdd(&cnt[dst[e]], 1);
}
__global__ void scan_kernel(const int* __restrict__ cnt, int* __restrict__ row,
                            int* __restrict__ fill) {
    __shared__ int s[1024];
    int tid = threadIdx.x;
    int base = tid * 16;
    int local[16];
    int sum = 0;
#pragma unroll
    for (int i = 0; i < 16; i++) { local[i] = sum; sum += cnt[base + i]; }
    s[tid] = sum;
    __syncthreads();
    for (int off = 1; off < 1024; off <<= 1) {
        int v = (tid >= off) ? s[tid - off] : 0;
        __syncthreads();
        s[tid] += v;
        __syncthreads();
    }
    int pre = (tid == 0) ? 0 : s[tid - 1];
#pragma unroll
    for (int i = 0; i < 16; i++) {
        int o = pre + local[i];
        row[base + i]  = o;
        fill[base + i] = o;
    }
    if (tid == 1023) row[NN] = s[1023];
}
__global__ void scatter_kernel(const int* __restrict__ src, const int* __restrict__ dst,
                               int E, int* __restrict__ fill, int* __restrict__ csrc) {
    int e = blockIdx.x * blockDim.x + threadIdx.x;
    if (e < E) {
        int p = atomicAdd(&fill[dst[e]], 1);
        csrc[p] = src[e];
    }
}

// ---------------- fp16 GEMM: C[M,1024] = A[M,K] @ W[1024,K]^T, fp16 out ----------------
// CTA tile 128x128x32, 128 threads, 4 warps (2m x 2n), warp tile 64x64, 2-stage.
__global__ __launch_bounds__(128, 2)
void hgemm_kernel(int K, const __half* __restrict__ A,
                  const __half* __restrict__ W, __half* __restrict__ C) {
    __shared__ __half As[2][128][40];
    __shared__ __half Bs[2][128][40];

    const int tid = threadIdx.x, lane = tid & 31, warp = tid >> 5;
    const int wm = (warp >> 1) << 6;    // 0 / 64
    const int wn = (warp & 1) << 6;     // 0 / 64
    const int bm = blockIdx.y << 7, bn = blockIdx.x << 7;

    // load mapping: thread t loads full row t of A and of B (4x 16B each)
    const int r = tid;
    const __half* Ag = A + (size_t)(bm + r) * K;
    const __half* Wg = W + (size_t)(bn + r) * K;
    const uint32_t sA = smem_u32(&As[0][0][0]);
    const uint32_t sB = smem_u32(&Bs[0][0][0]);
    const uint32_t dA = sA + (uint32_t)(r * 40) * 2;
    const uint32_t dB = sB + (uint32_t)(r * 40) * 2;

#define LOADCHUNK(buf, k0) do {                                        \
        _Pragma("unroll")                                              \
        for (int _q = 0; _q < 4; _q++) {                               \
            cp16(dA + (buf) * 10240u + _q * 16u, Ag + (k0) + _q * 8);  \
            cp16(dB + (buf) * 10240u + _q * 16u, Wg + (k0) + _q * 8);  \
        }                                                              \
        asm volatile("cp.async.commit_group;" ::: "memory");           \
    } while (0)

    float c[4][8][4] = {};

    const int aRow  = wm + (lane & 15);
    const int aColH = (lane >> 4) << 3;
    const int bRow0 = wn + ((lane >> 4) << 3) + (lane & 7);
    const int bColH = ((lane >> 3) & 1) << 3;

    LOADCHUNK(0, 0);

    const int KT = K >> 5;
    for (int kt = 0; kt < KT; kt++) {
        const int buf = kt & 1;
        if (kt + 1 < KT) {
            LOADCHUNK(buf ^ 1, (kt + 1) << 5);
            asm volatile("cp.async.wait_group 1;" ::: "memory");
        } else {
            asm volatile("cp.async.wait_group 0;" ::: "memory");
        }
        __syncthreads();

        const uint32_t aBase = sA + buf * 10240u;
        const uint32_t bBase = sB + buf * 10240u;
#pragma unroll
        for (int ks = 0; ks < 2; ks++) {
            uint32_t a[4][4];
#pragma unroll
            for (int mt = 0; mt < 4; mt++) {
                uint32_t addr = aBase + (uint32_t)((aRow + mt * 16) * 40 + ks * 16 + aColH) * 2;
                asm volatile("ldmatrix.sync.aligned.m8n8.x4.shared.b16 {%0,%1,%2,%3}, [%4];"
                    : "=r"(a[mt][0]), "=r"(a[mt][1]), "=r"(a[mt][2]), "=r"(a[mt][3])
                    : "r"(addr));
            }
            uint32_t b[4][4];
#pragma unroll
            for (int p = 0; p < 4; p++) {
                uint32_t addr = bBase + (uint32_t)((bRow0 + p * 16) * 40 + ks * 16 + bColH) * 2;
                asm volatile("ldmatrix.sync.aligned.m8n8.x4.shared.b16 {%0,%1,%2,%3}, [%4];"
                    : "=r"(b[p][0]), "=r"(b[p][1]), "=r"(b[p][2]), "=r"(b[p][3])
                    : "r"(addr));
            }
#pragma unroll
            for (int mt = 0; mt < 4; mt++)
#pragma unroll
                for (int nt = 0; nt < 8; nt++) {
                    const uint32_t b0 = b[nt >> 1][(nt & 1) * 2];
                    const uint32_t b1 = b[nt >> 1][(nt & 1) * 2 + 1];
                    asm volatile(
                        "mma.sync.aligned.m16n8k16.row.col.f32.f16.f16.f32 "
                        "{%0,%1,%2,%3},{%4,%5,%6,%7},{%8,%9},{%0,%1,%2,%3};"
                        : "+f"(c[mt][nt][0]), "+f"(c[mt][nt][1]),
                          "+f"(c[mt][nt][2]), "+f"(c[mt][nt][3])
                        : "r"(a[mt][0]), "r"(a[mt][1]), "r"(a[mt][2]), "r"(a[mt][3]),
                          "r"(b0), "r"(b1));
                }
        }
        __syncthreads();
    }
#undef LOADCHUNK

    // epilogue: fp16 output
    const int g = lane >> 2, t = lane & 3;
#pragma unroll
    for (int mt = 0; mt < 4; mt++) {
        int r0 = bm + wm + mt * 16 + g;
#pragma unroll
        for (int nt = 0; nt < 8; nt++) {
            int col = bn + wn + nt * 8 + 2 * t;
            *(__half2*)(C + (size_t)r0 * NTOT + col) =
                __floats2half2_rn(c[mt][nt][0], c[mt][nt][1]);
            *(__half2*)(C + (size_t)(r0 + 8) * NTOT + col) =
                __floats2half2_rn(c[mt][nt][2], c[mt][nt][3]);
        }
    }
}

// ---------------- fused GATv2 attention + online-softmax aggregation (fp16 in) ----------------
__global__ __launch_bounds__(256)
void gat_agg_kernel(const __half* __restrict__ xlr,
                    const int* __restrict__ row, const int* __restrict__ csrc,
                    const float* __restrict__ att, const float* __restrict__ bias,
                    float* __restrict__ out, int concat) {
    int warp = (blockIdx.x * blockDim.x + threadIdx.x) >> 5;
    int lane = threadIdx.x & 31;
    int fb = ((lane >> 2) << 6) + ((lane & 3) << 4);

    float attr[16], xrr[16], acc[16];
    {
        const float4* ap = (const float4*)(att + fb);
#pragma unroll
        for (int q = 0; q < 4; q++) {
            float4 a = ap[q];
            attr[q * 4 + 0] = a.x; attr[q * 4 + 1] = a.y; attr[q * 4 + 2] = a.z; attr[q * 4 + 3] = a.w;
        }
        const uint4* rp = (const uint4*)(xlr + (size_t)warp * NTOT + 512 + fb);
#pragma unroll
        for (int q = 0; q < 2; q++) {
            uint4 v = rp[q];
            float2 f0 = __half22float2(*(__half2*)&v.x);
            float2 f1 = __half22float2(*(__half2*)&v.y);
            float2 f2 = __half22float2(*(__half2*)&v.z);
            float2 f3 = __half22float2(*(__half2*)&v.w);
            xrr[q * 8 + 0] = f0.x; xrr[q * 8 + 1] = f0.y;
            xrr[q * 8 + 2] = f1.x; xrr[q * 8 + 3] = f1.y;
            xrr[q * 8 + 4] = f2.x; xrr[q * 8 + 5] = f2.y;
            xrr[q * 8 + 6] = f3.x; xrr[q * 8 + 7] = f3.y;
        }
    }
#pragma unroll
    for (int k = 0; k < 16; k++) acc[k] = 0.f;

    float m = -CUDART_INF_F, den = 0.f;
    int j0 = row[warp], j1 = row[warp + 1];

    for (int j = j0; j < j1; j++) {
        int s = csrc[j];
        float xlv[16];
        const uint4* lp = (const uint4*)(xlr + (size_t)s * NTOT + fb);
#pragma unroll
        for (int q = 0; q < 2; q++) {
            uint4 v = lp[q];
            float2 f0 = __half22float2(*(__half2*)&v.x);
            float2 f1 = __half22float2(*(__half2*)&v.y);
            float2 f2 = __half22float2(*(__half2*)&v.z);
            float2 f3 = __half22float2(*(__half2*)&v.w);
            xlv[q * 8 + 0] = f0.x; xlv[q * 8 + 1] = f0.y;
            xlv[q * 8 + 2] = f1.x; xlv[q * 8 + 3] = f1.y;
            xlv[q * 8 + 4] = f2.x; xlv[q * 8 + 5] = f2.y;
            xlv[q * 8 + 6] = f3.x; xlv[q * 8 + 7] = f3.y;
        }
        float p = 0.f;
#pragma unroll
        for (int k = 0; k < 16; k++) {
            float tt = xlv[k] + xrr[k];
            tt = (tt > 0.f) ? tt : 0.2f * tt;
            p += attr[k] * tt;
        }
        p += __shfl_xor_sync(0xffffffffu, p, 1);
        p += __shfl_xor_sync(0xffffffffu, p, 2);
        float mn = fmaxf(m, p);
        float scale = __expf(m - mn);
        float w = __expf(p - mn);
        den = den * scale + w;
#pragma unroll
        for (int k = 0; k < 16; k++) acc[k] = acc[k] * scale + w * xlv[k];
        m = mn;
    }

    float inv = 1.f / (den + 1e-16f);
    if (concat) {
        float* op = out + (size_t)warp * DD + fb;
#pragma unroll
        for (int q = 0; q < 4; q++) {
            float4 v;
            v.x = acc[q * 4 + 0] * inv + bias[fb + q * 4 + 0];
            v.y = acc[q * 4 + 1] * inv + bias[fb + q * 4 + 1];
            v.z = acc[q * 4 + 2] * inv + bias[fb + q * 4 + 2];
            v.w = acc[q * 4 + 3] * inv + bias[fb + q * 4 + 3];
            *(float4*)(op + q * 4) = v;
        }
    } else {
        float r[16];
#pragma unroll
        for (int k = 0; k < 16; k++) r[k] = acc[k] * inv;
#pragma unroll
        for (int off = 4; off < 32; off <<= 1)
#pragma unroll
            for (int k = 0; k < 16; k++) r[k] += __shfl_xor_sync(0xffffffffu, r[k], off);
        if (lane < 4) {
            int fo = lane << 4;
            float* op = out + (size_t)warp * FF + fo;
#pragma unroll
            for (int k = 0; k < 16; k++)
                op[k] = r[k] * 0.125f + bias[fo + k];
        }
    }
}

// ---------------- GraphNorm + ReLU; single stats pass (S, Q) ----------------
__global__ void graphnorm_relu_kernel(const float* __restrict__ in, const float* __restrict__ w,
                                      const float* __restrict__ b, const float* __restrict__ ms,
                                      float* __restrict__ outf, __half* __restrict__ outh,
                                      int D, int mode) {
    int g = blockIdx.x;
    const float* base = in + (size_t)g * NPG * D;
    for (int d = threadIdx.x; d < D; d += blockDim.x) {
        float s = 0.f, q = 0.f;
#pragma unroll 8
        for (int i = 0; i < NPG; i++) {
            float x = base[(size_t)i * D + d];
            s += x;
            q += x * x;
        }
        float mean = s * (1.f / NPG);
        float msm = ms[d] * mean;
        float v = q * (1.f / NPG) - 2.f * msm * mean + msm * msm;
        float invs = rsqrtf(v + 1e-5f);
        float ww = w[d], bb = b[d];
        if (mode == 1) {
            __half* ob = outh + (size_t)g * NPG * D;
#pragma unroll 8
            for (int i = 0; i < NPG; i++) {
                float xc = base[(size_t)i * D + d] - msm;
                float o = fmaxf(ww * xc * invs + bb, 0.f);
                ob[(size_t)i * D + d] = __float2half_rn(o);
            }
        } else {
            float* ob = outf + (size_t)g * NPG * D;
#pragma unroll 8
            for (int i = 0; i < NPG; i++) {
                float xc = base[(size_t)i * D + d] - msm;
                ob[(size_t)i * D + d] = fmaxf(ww * xc * invs + bb, 0.f);
            }
        }
    }
}

// ---------------- global mean pool + final linear ----------------
__global__ void pool_linear_kernel(const float* __restrict__ h, const float* __restrict__ Wlin,
                                   const float* __restrict__ blin, float* __restrict__ out) {
    int g = blockIdx.x;
    __shared__ float p[FF];
    int t = threadIdx.x;
    float s = 0.f;
#pragma unroll 8
    for (int i = 0; i < NPG; i++) s += h[(size_t)(g * NPG + i) * FF + t];
    p[t] = s * (1.f / NPG);
    __syncthreads();
    if (t < 2) {
        float o = blin[t];
#pragma unroll
        for (int f = 0; f < FF; f++) o += p[f] * Wlin[f * 2 + t];
        out[g * 2 + t] = o;
    }
}

// ---------------- host launcher ----------------
extern "C" void kernel_launch(void* const* d_in, const int* in_sizes, int n_in,
                              void* d_out, int out_size) {
    const float* x     = (const float*)d_in[0];
    const int*   esrc  = (const int*)d_in[1];
    const int*   edst  = (const int*)d_in[2];
    const float* Wl[3]  = {(const float*)d_in[4],  (const float*)d_in[11], (const float*)d_in[18]};
    const float* Wr[3]  = {(const float*)d_in[5],  (const float*)d_in[12], (const float*)d_in[19]};
    const float* att[3] = {(const float*)d_in[6],  (const float*)d_in[13], (const float*)d_in[20]};
    const float* bia[3] = {(const float*)d_in[7],  (const float*)d_in[14], (const float*)d_in[21]};
    const float* gnw[3] = {(const float*)d_in[8],  (const float*)d_in[15], (const float*)d_in[22]};
    const float* gnb[3] = {(const float*)d_in[9],  (const float*)d_in[16], (const float*)d_in[23]};
    const float* gnm[3] = {(const float*)d_in[10], (const float*)d_in[17], (const float*)d_in[24]};
    const float* Wlin = (const float*)d_in[25];
    const float* blin = (const float*)d_in[26];
    float* out = (float*)d_out;

    int E = in_sizes[1];

    float *A, *B;
    __half *XLRh, *Xh, *Bh, *Wh;
    int *cnt, *row, *fill, *csrc;
    cudaGetSymbolAddress((void**)&XLRh, g_XLRh);
    cudaGetSymbolAddress((void**)&A,    g_A);
    cudaGetSymbolAddress((void**)&B,    g_B);
    cudaGetSymbolAddress((void**)&Xh,   g_Xh);
    cudaGetSymbolAddress((void**)&Bh,   g_Bh);
    cudaGetSymbolAddress((void**)&Wh,   g_Wh);
    cudaGetSymbolAddress((void**)&cnt,  g_cnt);
    cudaGetSymbolAddress((void**)&row,  g_row);
    cudaGetSymbolAddress((void**)&fill, g_fill);
    cudaGetSymbolAddress((void**)&csrc, g_csrc);

    // weight prep
    const int Koff[3] = {256, 512, 512};
    __half* WhL[3] = {Wh, Wh + 262144, Wh + 786432};
    for (int l = 0; l < 3; l++) {
        int K = Koff[l];
        dim3 tg(16, K / 32), tb(32, 8);
        transpose_half_kernel<<<tg, tb>>>(Wl[l], WhL[l], K);
        transpose_half_kernel<<<tg, tb>>>(Wr[l], WhL[l] + 512 * K, K);
    }
    to_half_kernel<<<(NN * 256 / 4 + 255) / 256, 256>>>((const float4*)x, (__half2*)Xh, NN * 256 / 4);

    // CSR build
    zero_int_kernel<<<(NN + 255) / 256, 256>>>(cnt, NN);
    count_kernel<<<(E + 255) / 256, 256>>>(edst, E, cnt);
    scan_kernel<<<1, 1024>>>(cnt, row, fill);
    scatter_kernel<<<(E + 255) / 256, 256>>>(esrc, edst, E, fill, csrc);

    dim3 ggrid(NTOT / 128, NN / 128);     // (8, 128)
    const int agg_blocks = (NN * 32) / 256;

    // layer 1 (K=256)
    hgemm_kernel<<<ggrid, 128>>>(256, Xh, WhL[0], XLRh);
    gat_agg_kernel<<<agg_blocks, 256>>>(XLRh, row, csrc, att[0], bia[0], A, 1);
    graphnorm_relu_kernel<<<GG, 256>>>(A, gnw[0], gnb[0], gnm[0], nullptr, Bh, DD, 1);

    // layer 2 (K=512)
    hgemm_kernel<<<ggrid, 128>>>(512, Bh, WhL[1], XLRh);
    gat_agg_kernel<<<agg_blocks, 256>>>(XLRh, row, csrc, att[1], bia[1], A, 1);
    graphnorm_relu_kernel<<<GG, 256>>>(A, gnw[1], gnb[1], gnm[1], nullptr, Bh, DD, 1);

    // layer 3 (K=512, concat=False)
    hgemm_kernel<<<ggrid, 128>>>(512, Bh, WhL[2], XLRh);
    gat_agg_kernel<<<agg_blocks, 256>>>(XLRh, row, csrc, att[2], bia[2], A, 0);
    graphnorm_relu_kernel<<<GG, 256>>>(A, gnw[2], gnb[2], gnm[2], B, nullptr, FF, 0);

    // pool + linear
    pool_linear_kernel<<<GG, 64>>>(B, Wlin, blin, out);
}

// round 8
// speedup vs baseline: 1.0928x; 1.0928x over previous
#include <cuda_runtime.h>
#include <cuda_fp16.h>
#include <math_constants.h>
#include <cstdint>

// ---------------- problem constants ----------------
#define NN 16384      // nodes
#define GG 256        // graphs
#define NPG 64        // nodes per graph
#define FF 64         // per-head features
#define DD 512        // H*F
#define NTOT 1024     // fused Wl|Wr output width
#define EMAX 147456

// ---------------- scratch ----------------
__device__ __half g_XLRh[NN * NTOT];    // fused xl|xr GEMM output (fp16)
__device__ float  g_A [NN * DD];        // agg output
__device__ float  g_B [NN * FF];        // layer-3 norm output
__device__ __half g_Xh[NN * 256];       // fp16 input x
__device__ __half g_Bh[NN * DD];        // fp16 norm outputs
__device__ __half g_Wh[1310720];        // fp16 transposed weights [1024][K] x 3
__device__ int    g_cnt [NN];
__device__ int    g_row [NN + 1];
__device__ int    g_fill[NN];
__device__ int    g_csrc[EMAX];

// ---------------- helpers ----------------
__device__ __forceinline__ uint32_t smem_u32(const void* p) {
    return (uint32_t)__cvta_generic_to_shared(p);
}
__device__ __forceinline__ void cp16(uint32_t d, const void* s) {
    asm volatile("cp.async.cg.shared.global [%0], [%1], 16;" :: "r"(d), "l"(s));
}

// ---------------- prep kernels ----------------
__global__ void to_half_kernel(const float4* __restrict__ in, __half2* __restrict__ out, int n4) {
    int i = blockIdx.x * blockDim.x + threadIdx.x;
    if (i < n4) {
        float4 v = in[i];
        out[i * 2]     = __floats2half2_rn(v.x, v.y);
        out[i * 2 + 1] = __floats2half2_rn(v.z, v.w);
    }
}

// all 6 weight transposes in ONE launch. z selects matrix.
// W [K,512] row-major fp32 -> Wt [512,K] K-major fp16 at per-matrix offset.
__global__ void transpose_all_kernel(const float* __restrict__ W0, const float* __restrict__ W1,
                                     const float* __restrict__ W2, const float* __restrict__ W3,
                                     const float* __restrict__ W4, const float* __restrict__ W5,
                                     __half* __restrict__ Wh) {
    __shared__ float t[32][33];
    const int z = blockIdx.z;
    const int K = (z < 2) ? 256 : 512;
    const int by = blockIdx.y * 32;
    if (by >= K) return;
    const float* W;
    uint32_t off;
    switch (z) {
        case 0: W = W0; off = 0u;       break;
        case 1: W = W1; off = 131072u;  break;
        case 2: W = W2; off = 262144u;  break;
        case 3: W = W3; off = 524288u;  break;
        case 4: W = W4; off = 786432u;  break;
        default:W = W5; off = 1048576u; break;
    }
    __half* Wt = Wh + off;
    const int bx = blockIdx.x * 32;
    const int x = threadIdx.x, y = threadIdx.y;
#pragma unroll
    for (int j = 0; j < 32; j += 8) t[y + j][x] = W[(size_t)(by + y + j) * DD + bx + x];
    __syncthreads();
#pragma unroll
    for (int j = 0; j < 32; j += 8)
        Wt[(size_t)(bx + y + j) * K + by + x] = __float2half_rn(t[x][y + j]);
}

// ---------------- CSR build ----------------
__global__ void zero_int_kernel(int* p, int n) {
    int i = blockIdx.x * blockDim.x + threadIdx.x;
    if (i < n) p[i] = 0;
}
__global__ void count_kernel(const int* __restrict__ dst, int E, int* __restrict__ cnt) {
    int e = blockIdx.x * blockDim.x + threadIdx.x;
    if (e < E) atomicAdd(&cnt[dst[e]], 1);
}
__global__ void scan_kernel(const int* __restrict__ cnt, int* __restrict__ row,
                            int* __restrict__ fill) {
    __shared__ int s[1024];
    int tid = threadIdx.x;
    int base = tid * 16;
    int local[16];
    int sum = 0;
#pragma unroll
    for (int i = 0; i < 16; i++) { local[i] = sum; sum += cnt[base + i]; }
    s[tid] = sum;
    __syncthreads();
    for (int off = 1; off < 1024; off <<= 1) {
        int v = (tid >= off) ? s[tid - off] : 0;
        __syncthreads();
        s[tid] += v;
        __syncthreads();
    }
    int pre = (tid == 0) ? 0 : s[tid - 1];
#pragma unroll
    for (int i = 0; i < 16; i++) {
        int o = pre + local[i];
        row[base + i]  = o;
        fill[base + i] = o;
    }
    if (tid == 1023) row[NN] = s[1023];
}
__global__ void scatter_kernel(const int* __restrict__ src, const int* __restrict__ dst,
                               int E, int* __restrict__ fill, int* __restrict__ csrc) {
    int e = blockIdx.x * blockDim.x + threadIdx.x;
    if (e < E) {
        int p = atomicAdd(&fill[dst[e]], 1);
        csrc[p] = src[e];
    }
}

// ---------------- fp16 GEMM: C[M,1024] = A[M,K] @ W[1024,K]^T, fp16 out ----------------
// CTA tile 128x128x32, 256 threads, 8 warps (2m x 4n), warp tile 64x32, 2-stage.
__global__ __launch_bounds__(256, 2)
void hgemm_kernel(int K, const __half* __restrict__ A,
                  const __half* __restrict__ W, __half* __restrict__ C) {
    __shared__ __half As[2][128][40];
    __shared__ __half Bs[2][128][40];

    const int tid = threadIdx.x, lane = tid & 31, warp = tid >> 5;
    const int wm = (warp >> 2) << 6;
    const int wn = (warp & 3) << 5;
    const int bm = blockIdx.y << 7, bn = blockIdx.x << 7;

    const int r = tid >> 1, sc = (tid & 1) << 4;
    const __half* Ag = A + (size_t)(bm + r) * K + sc;
    const __half* Wg = W + (size_t)(bn + r) * K + sc;
    const uint32_t sA = smem_u32(&As[0][0][0]);
    const uint32_t sB = smem_u32(&Bs[0][0][0]);
    const uint32_t dA = sA + (uint32_t)(r * 40 + sc) * 2;
    const uint32_t dB = sB + (uint32_t)(r * 40 + sc) * 2;

#define LOADCHUNK(buf, k0) do {                                  \
        cp16(dA + (buf) * 10240u,       Ag + (k0));              \
        cp16(dA + (buf) * 10240u + 16u, Ag + (k0) + 8);          \
        cp16(dB + (buf) * 10240u,       Wg + (k0));              \
        cp16(dB + (buf) * 10240u + 16u, Wg + (k0) + 8);          \
        asm volatile("cp.async.commit_group;" ::: "memory");     \
    } while (0)

    float c[4][4][4] = {};

    const int aRow  = wm + (lane & 15);
    const int aColH = (lane >> 4) << 3;
    const int bRow0 = wn + ((lane >> 4) << 3) + (lane & 7);
    const int bColH = ((lane >> 3) & 1) << 3;

    LOADCHUNK(0, 0);

    const int KT = K >> 5;
    for (int kt = 0; kt < KT; kt++) {
        const int buf = kt & 1;
        if (kt + 1 < KT) {
            LOADCHUNK(buf ^ 1, (kt + 1) << 5);
            asm volatile("cp.async.wait_group 1;" ::: "memory");
        } else {
            asm volatile("cp.async.wait_group 0;" ::: "memory");
        }
        __syncthreads();

        const uint32_t aBase = sA + buf * 10240u;
        const uint32_t bBase = sB + buf * 10240u;
#pragma unroll
        for (int ks = 0; ks < 2; ks++) {
            uint32_t a[4][4];
#pragma unroll
            for (int mt = 0; mt < 4; mt++) {
                uint32_t addr = aBase + (uint32_t)((aRow + mt * 16) * 40 + ks * 16 + aColH) * 2;
                asm volatile("ldmatrix.sync.aligned.m8n8.x4.shared.b16 {%0,%1,%2,%3}, [%4];"
                    : "=r"(a[mt][0]), "=r"(a[mt][1]), "=r"(a[mt][2]), "=r"(a[mt][3])
                    : "r"(addr));
            }
            uint32_t b[2][4];
#pragma unroll
            for (int p = 0; p < 2; p++) {
                uint32_t addr = bBase + (uint32_t)((bRow0 + p * 16) * 40 + ks * 16 + bColH) * 2;
                asm volatile("ldmatrix.sync.aligned.m8n8.x4.shared.b16 {%0,%1,%2,%3}, [%4];"
                    : "=r"(b[p][0]), "=r"(b[p][1]), "=r"(b[p][2]), "=r"(b[p][3])
                    : "r"(addr));
            }
#pragma unroll
            for (int mt = 0; mt < 4; mt++)
#pragma unroll
                for (int nt = 0; nt < 4; nt++) {
                    const uint32_t b0 = b[nt >> 1][(nt & 1) * 2];
                    const uint32_t b1 = b[nt >> 1][(nt & 1) * 2 + 1];
                    asm volatile(
                        "mma.sync.aligned.m16n8k16.row.col.f32.f16.f16.f32 "
                        "{%0,%1,%2,%3},{%4,%5,%6,%7},{%8,%9},{%0,%1,%2,%3};"
                        : "+f"(c[mt][nt][0]), "+f"(c[mt][nt][1]),
                          "+f"(c[mt][nt][2]), "+f"(c[mt][nt][3])
                        : "r"(a[mt][0]), "r"(a[mt][1]), "r"(a[mt][2]), "r"(a[mt][3]),
                          "r"(b0), "r"(b1));
                }
        }
        __syncthreads();
    }
#undef LOADCHUNK

    // epilogue: fp16 output
    const int g = lane >> 2, t = lane & 3;
#pragma unroll
    for (int mt = 0; mt < 4; mt++) {
        int r0 = bm + wm + mt * 16 + g;
#pragma unroll
        for (int nt = 0; nt < 4; nt++) {
            int col = bn + wn + nt * 8 + 2 * t;
            *(__half2*)(C + (size_t)r0 * NTOT + col) =
                __floats2half2_rn(c[mt][nt][0], c[mt][nt][1]);
            *(__half2*)(C + (size_t)(r0 + 8) * NTOT + col) =
                __floats2half2_rn(c[mt][nt][2], c[mt][nt][3]);
        }
    }
}

// ---------------- fused GATv2 attention + online-softmax aggregation (fp16 in) ----------------
__global__ __launch_bounds__(256)
void gat_agg_kernel(const __half* __restrict__ xlr,
                    const int* __restrict__ row, const int* __restrict__ csrc,
                    const float* __restrict__ att, const float* __restrict__ bias,
                    float* __restrict__ out, int concat) {
    int warp = (blockIdx.x * blockDim.x + threadIdx.x) >> 5;
    int lane = threadIdx.x & 31;
    int fb = ((lane >> 2) << 6) + ((lane & 3) << 4);

    float attr[16], xrr[16], acc[16];
    {
        const float4* ap = (const float4*)(att + fb);
#pragma unroll
        for (int q = 0; q < 4; q++) {
            float4 a = ap[q];
            attr[q * 4 + 0] = a.x; attr[q * 4 + 1] = a.y; attr[q * 4 + 2] = a.z; attr[q * 4 + 3] = a.w;
        }
        const uint4* rp = (const uint4*)(xlr + (size_t)warp * NTOT + 512 + fb);
#pragma unroll
        for (int q = 0; q < 2; q++) {
            uint4 v = rp[q];
            float2 f0 = __half22float2(*(__half2*)&v.x);
            float2 f1 = __half22float2(*(__half2*)&v.y);
            float2 f2 = __half22float2(*(__half2*)&v.z);
            float2 f3 = __half22float2(*(__half2*)&v.w);
            xrr[q * 8 + 0] = f0.x; xrr[q * 8 + 1] = f0.y;
            xrr[q * 8 + 2] = f1.x; xrr[q * 8 + 3] = f1.y;
            xrr[q * 8 + 4] = f2.x; xrr[q * 8 + 5] = f2.y;
            xrr[q * 8 + 6] = f3.x; xrr[q * 8 + 7] = f3.y;
        }
    }
#pragma unroll
    for (int k = 0; k < 16; k++) acc[k] = 0.f;

    float m = -CUDART_INF_F, den = 0.f;
    int j0 = row[warp], j1 = row[warp + 1];

    for (int j = j0; j < j1; j++) {
        int s = csrc[j];
        float xlv[16];
        const uint4* lp = (const uint4*)(xlr + (size_t)s * NTOT + fb);
#pragma unroll
        for (int q = 0; q < 2; q++) {
            uint4 v = lp[q];
            float2 f0 = __half22float2(*(__half2*)&v.x);
            float2 f1 = __half22float2(*(__half2*)&v.y);
            float2 f2 = __half22float2(*(__half2*)&v.z);
            float2 f3 = __half22float2(*(__half2*)&v.w);
            xlv[q * 8 + 0] = f0.x; xlv[q * 8 + 1] = f0.y;
            xlv[q * 8 + 2] = f1.x; xlv[q * 8 + 3] = f1.y;
            xlv[q * 8 + 4] = f2.x; xlv[q * 8 + 5] = f2.y;
            xlv[q * 8 + 6] = f3.x; xlv[q * 8 + 7] = f3.y;
        }
        float p = 0.f;
#pragma unroll
        for (int k = 0; k < 16; k++) {
            float tt = xlv[k] + xrr[k];
            tt = (tt > 0.f) ? tt : 0.2f * tt;
            p += attr[k] * tt;
        }
        p += __shfl_xor_sync(0xffffffffu, p, 1);
        p += __shfl_xor_sync(0xffffffffu, p, 2);
        float mn = fmaxf(m, p);
        float scale = __expf(m - mn);
        float w = __expf(p - mn);
        den = den * scale + w;
#pragma unroll
        for (int k = 0; k < 16; k++) acc[k] = acc[k] * scale + w * xlv[k];
        m = mn;
    }

    float inv = 1.f / (den + 1e-16f);
    if (concat) {
        float* op = out + (size_t)warp * DD + fb;
#pragma unroll
        for (int q = 0; q < 4; q++) {
            float4 v;
            v.x = acc[q * 4 + 0] * inv + bias[fb + q * 4 + 0];
            v.y = acc[q * 4 + 1] * inv + bias[fb + q * 4 + 1];
            v.z = acc[q * 4 + 2] * inv + bias[fb + q * 4 + 2];
            v.w = acc[q * 4 + 3] * inv + bias[fb + q * 4 + 3];
            *(float4*)(op + q * 4) = v;
        }
    } else {
        float r[16];
#pragma unroll
        for (int k = 0; k < 16; k++) r[k] = acc[k] * inv;
#pragma unroll
        for (int off = 4; off < 32; off <<= 1)
#pragma unroll
            for (int k = 0; k < 16; k++) r[k] += __shfl_xor_sync(0xffffffffu, r[k], off);
        if (lane < 4) {
            int fo = lane << 4;
            float* op = out + (size_t)warp * FF + fo;
#pragma unroll
            for (int k = 0; k < 16; k++)
                op[k] = r[k] * 0.125f + bias[fo + k];
        }
    }
}

// ---------------- GraphNorm + ReLU; single stats pass ----------------
__global__ void graphnorm_relu_kernel(const float* __restrict__ in, const float* __restrict__ w,
                                      const float* __restrict__ b, const float* __restrict__ ms,
                                      float* __restrict__ outf, __half* __restrict__ outh,
                                      int D, int mode) {
    int g = blockIdx.x;
    const float* base = in + (size_t)g * NPG * D;
    for (int d = threadIdx.x; d < D; d += blockDim.x) {
        float s = 0.f, q = 0.f;
#pragma unroll 8
        for (int i = 0; i < NPG; i++) {
            float x = base[(size_t)i * D + d];
            s += x;
            q += x * x;
        }
        float mean = s * (1.f / NPG);
        float msm = ms[d] * mean;
        float v = q * (1.f / NPG) - 2.f * msm * mean + msm * msm;
        float invs = rsqrtf(v + 1e-5f);
        float ww = w[d], bb = b[d];
        if (mode == 1) {
            __half* ob = outh + (size_t)g * NPG * D;
#pragma unroll 8
            for (int i = 0; i < NPG; i++) {
                float xc = base[(size_t)i * D + d] - msm;
                float o = fmaxf(ww * xc * invs + bb, 0.f);
                ob[(size_t)i * D + d] = __float2half_rn(o);
            }
        } else {
            float* ob = outf + (size_t)g * NPG * D;
#pragma unroll 8
            for (int i = 0; i < NPG; i++) {
                float xc = base[(size_t)i * D + d] - msm;
                ob[(size_t)i * D + d] = fmaxf(ww * xc * invs + bb, 0.f);
            }
        }
    }
}

// ---------------- global mean pool + final linear ----------------
__global__ void pool_linear_kernel(const float* __restrict__ h, const float* __restrict__ Wlin,
                                   const float* __restrict__ blin, float* __restrict__ out) {
    int g = blockIdx.x;
    __shared__ float p[FF];
    int t = threadIdx.x;
    float s = 0.f;
#pragma unroll 8
    for (int i = 0; i < NPG; i++) s += h[(size_t)(g * NPG + i) * FF + t];
    p[t] = s * (1.f / NPG);
    __syncthreads();
    if (t < 2) {
        float o = blin[t];
#pragma unroll
        for (int f = 0; f < FF; f++) o += p[f] * Wlin[f * 2 + t];
        out[g * 2 + t] = o;
    }
}

// ---------------- host launcher ----------------
extern "C" void kernel_launch(void* const* d_in, const int* in_sizes, int n_in,
                              void* d_out, int out_size) {
    const float* x     = (const float*)d_in[0];
    const int*   esrc  = (const int*)d_in[1];
    const int*   edst  = (const int*)d_in[2];
    const float* Wl[3]  = {(const float*)d_in[4],  (const float*)d_in[11], (const float*)d_in[18]};
    const float* Wr[3]  = {(const float*)d_in[5],  (const float*)d_in[12], (const float*)d_in[19]};
    const float* att[3] = {(const float*)d_in[6],  (const float*)d_in[13], (const float*)d_in[20]};
    const float* bia[3] = {(const float*)d_in[7],  (const float*)d_in[14], (const float*)d_in[21]};
    const float* gnw[3] = {(const float*)d_in[8],  (const float*)d_in[15], (const float*)d_in[22]};
    const float* gnb[3] = {(const float*)d_in[9],  (const float*)d_in[16], (const float*)d_in[23]};
    const float* gnm[3] = {(const float*)d_in[10], (const float*)d_in[17], (const float*)d_in[24]};
    const float* Wlin = (const float*)d_in[25];
    const float* blin = (const float*)d_in[26];
    float* out = (float*)d_out;

    int E = in_sizes[1];

    float *A, *B;
    __half *XLRh, *Xh, *Bh, *Wh;
    int *cnt, *row, *fill, *csrc;
    cudaGetSymbolAddress((void**)&XLRh, g_XLRh);
    cudaGetSymbolAddress((void**)&A,    g_A);
    cudaGetSymbolAddress((void**)&B,    g_B);
    cudaGetSymbolAddress((void**)&Xh,   g_Xh);
    cudaGetSymbolAddress((void**)&Bh,   g_Bh);
    cudaGetSymbolAddress((void**)&Wh,   g_Wh);
    cudaGetSymbolAddress((void**)&cnt,  g_cnt);
    cudaGetSymbolAddress((void**)&row,  g_row);
    cudaGetSymbolAddress((void**)&fill, g_fill);
    cudaGetSymbolAddress((void**)&csrc, g_csrc);

    // prep: all weight transposes in one launch + x conversion
    transpose_all_kernel<<<dim3(16, 16, 6), dim3(32, 8)>>>(
        Wl[0], Wr[0], Wl[1], Wr[1], Wl[2], Wr[2], Wh);
    to_half_kernel<<<(NN * 256 / 4 + 255) / 256, 256>>>((const float4*)x, (__half2*)Xh, NN * 256 / 4);

    // CSR build
    zero_int_kernel<<<(NN + 255) / 256, 256>>>(cnt, NN);
    count_kernel<<<(E + 255) / 256, 256>>>(edst, E, cnt);
    scan_kernel<<<1, 1024>>>(cnt, row, fill);
    scatter_kernel<<<(E + 255) / 256, 256>>>(esrc, edst, E, fill, csrc);

    __half* WhL[3] = {Wh, Wh + 262144, Wh + 786432};
    dim3 ggrid(NTOT / 128, NN / 128);     // (8, 128)
    const int agg_blocks = (NN * 32) / 256;

    // layer 1 (K=256)
    hgemm_kernel<<<ggrid, 256>>>(256, Xh, WhL[0], XLRh);
    gat_agg_kernel<<<agg_blocks, 256>>>(XLRh, row, csrc, att[0], bia[0], A, 1);
    graphnorm_relu_kernel<<<GG, 256>>>(A, gnw[0], gnb[0], gnm[0], nullptr, Bh, DD, 1);

    // layer 2 (K=512)
    hgemm_kernel<<<ggrid, 256>>>(512, Bh, WhL[1], XLRh);
    gat_agg_kernel<<<agg_blocks, 256>>>(XLRh, row, csrc, att[1], bia[1], A, 1);
    graphnorm_relu_kernel<<<GG, 256>>>(A, gnw[1], gnb[1], gnm[1], nullptr, Bh, DD, 1);

    // layer 3 (K=512, concat=False)
    hgemm_kernel<<<ggrid, 256>>>(512, Bh, WhL[2], XLRh);
    gat_agg_kernel<<<agg_blocks, 256>>>(XLRh, row, csrc, att[2], bia[2], A, 0);
    graphnorm_relu_kernel<<<GG, 256>>>(A, gnw[2], gnb[2], gnm[2], B, nullptr, FF, 0);

    // pool + linear
    pool_linear_kernel<<<GG, 64>>>(B, Wlin, blin, out);
}

// round 9
// speedup vs baseline: 1.2190x; 1.1155x over previous
#include <cuda_runtime.h>
#include <cuda_fp16.h>
#include <math_constants.h>
#include <cstdint>

// ---------------- problem constants ----------------
#define NN 16384      // nodes
#define GG 256        // graphs
#define NPG 64        // nodes per graph
#define FF 64         // per-head features
#define DD 512        // H*F
#define NTOT 1024     // fused Wl|Wr output width
#define EMAX 147456

// ---------------- scratch ----------------
__device__ __half g_XLRh[NN * NTOT];    // fused xl|xr GEMM output (fp16)
__device__ __half g_Xh[NN * 256];       // fp16 input x
__device__ __half g_Bh[NN * DD];        // fp16 norm outputs (next GEMM input)
__device__ __half g_Wh[1310720];        // fp16 transposed weights [1024][K] x 3
__device__ int    g_cnt [NN];
__device__ int    g_row [NN + 1];
__device__ int    g_fill[NN];
__device__ int    g_csrc[EMAX];

// ---------------- helpers ----------------
__device__ __forceinline__ uint32_t smem_u32(const void* p) {
    return (uint32_t)__cvta_generic_to_shared(p);
}
__device__ __forceinline__ void cp16(uint32_t d, const void* s) {
    asm volatile("cp.async.cg.shared.global [%0], [%1], 16;" :: "r"(d), "l"(s));
}

// ---------------- prep kernels ----------------
__global__ void to_half_kernel(const float4* __restrict__ in, __half2* __restrict__ out, int n4) {
    int i = blockIdx.x * blockDim.x + threadIdx.x;
    if (i < n4) {
        float4 v = in[i];
        out[i * 2]     = __floats2half2_rn(v.x, v.y);
        out[i * 2 + 1] = __floats2half2_rn(v.z, v.w);
    }
}

__global__ void transpose_all_kernel(const float* __restrict__ W0, const float* __restrict__ W1,
                                     const float* __restrict__ W2, const float* __restrict__ W3,
                                     const float* __restrict__ W4, const float* __restrict__ W5,
                                     __half* __restrict__ Wh) {
    __shared__ float t[32][33];
    const int z = blockIdx.z;
    const int K = (z < 2) ? 256 : 512;
    const int by = blockIdx.y * 32;
    if (by >= K) return;
    const float* W;
    uint32_t off;
    switch (z) {
        case 0: W = W0; off = 0u;       break;
        case 1: W = W1; off = 131072u;  break;
        case 2: W = W2; off = 262144u;  break;
        case 3: W = W3; off = 524288u;  break;
        case 4: W = W4; off = 786432u;  break;
        default:W = W5; off = 1048576u; break;
    }
    __half* Wt = Wh + off;
    const int bx = blockIdx.x * 32;
    const int x = threadIdx.x, y = threadIdx.y;
#pragma unroll
    for (int j = 0; j < 32; j += 8) t[y + j][x] = W[(size_t)(by + y + j) * DD + bx + x];
    __syncthreads();
#pragma unroll
    for (int j = 0; j < 32; j += 8)
        Wt[(size_t)(bx + y + j) * K + by + x] = __float2half_rn(t[x][y + j]);
}

// ---------------- CSR build ----------------
__global__ void zero_int_kernel(int* p, int n) {
    int i = blockIdx.x * blockDim.x + threadIdx.x;
    if (i < n) p[i] = 0;
}
__global__ void count_kernel(const int* __restrict__ dst, int E, int* __restrict__ cnt) {
    int e = blockIdx.x * blockDim.x + threadIdx.x;
    if (e < E) atomicAdd(&cnt[dst[e]], 1);
}
__global__ void scan_kernel(const int* __restrict__ cnt, int* __restrict__ row,
                            int* __restrict__ fill) {
    __shared__ int s[1024];
    int tid = threadIdx.x;
    int base = tid * 16;
    int local[16];
    int sum = 0;
#pragma unroll
    for (int i = 0; i < 16; i++) { local[i] = sum; sum += cnt[base + i]; }
    s[tid] = sum;
    __syncthreads();
    for (int off = 1; off < 1024; off <<= 1) {
        int v = (tid >= off) ? s[tid - off] : 0;
        __syncthreads();
        s[tid] += v;
        __syncthreads();
    }
    int pre = (tid == 0) ? 0 : s[tid - 1];
#pragma unroll
    for (int i = 0; i < 16; i++) {
        int o = pre + local[i];
        row[base + i]  = o;
        fill[base + i] = o;
    }
    if (tid == 1023) row[NN] = s[1023];
}
__global__ void scatter_kernel(const int* __restrict__ src, const int* __restrict__ dst,
                               int E, int* __restrict__ fill, int* __restrict__ csrc) {
    int e = blockIdx.x * blockDim.x + threadIdx.x;
    if (e < E) {
        int p = atomicAdd(&fill[dst[e]], 1);
        csrc[p] = src[e];
    }
}

// ---------------- fp16 GEMM: C[M,1024] = A[M,K] @ W[1024,K]^T, fp16 out ----------------
// CTA tile 128x128x32, 256 threads, 8 warps (2m x 4n), warp tile 64x32, 2-stage.
__global__ __launch_bounds__(256, 2)
void hgemm_kernel(int K, const __half* __restrict__ A,
                  const __half* __restrict__ W, __half* __restrict__ C) {
    __shared__ __half As[2][128][40];
    __shared__ __half Bs[2][128][40];

    const int tid = threadIdx.x, lane = tid & 31, warp = tid >> 5;
    const int wm = (warp >> 2) << 6;
    const int wn = (warp & 3) << 5;
    const int bm = blockIdx.y << 7, bn = blockIdx.x << 7;

    const int r = tid >> 1, sc = (tid & 1) << 4;
    const __half* Ag = A + (size_t)(bm + r) * K + sc;
    const __half* Wg = W + (size_t)(bn + r) * K + sc;
    const uint32_t sA = smem_u32(&As[0][0][0]);
    const uint32_t sB = smem_u32(&Bs[0][0][0]);
    const uint32_t dA = sA + (uint32_t)(r * 40 + sc) * 2;
    const uint32_t dB = sB + (uint32_t)(r * 40 + sc) * 2;

#define LOADCHUNK(buf, k0) do {                                  \
        cp16(dA + (buf) * 10240u,       Ag + (k0));              \
        cp16(dA + (buf) * 10240u + 16u, Ag + (k0) + 8);          \
        cp16(dB + (buf) * 10240u,       Wg + (k0));              \
        cp16(dB + (buf) * 10240u + 16u, Wg + (k0) + 8);          \
        asm volatile("cp.async.commit_group;" ::: "memory");     \
    } while (0)

    float c[4][4][4] = {};

    const int aRow  = wm + (lane & 15);
    const int aColH = (lane >> 4) << 3;
    const int bRow0 = wn + ((lane >> 4) << 3) + (lane & 7);
    const int bColH = ((lane >> 3) & 1) << 3;

    LOADCHUNK(0, 0);

    const int KT = K >> 5;
    for (int kt = 0; kt < KT; kt++) {
        const int buf = kt & 1;
        if (kt + 1 < KT) {
            LOADCHUNK(buf ^ 1, (kt + 1) << 5);
            asm volatile("cp.async.wait_group 1;" ::: "memory");
        } else {
            asm volatile("cp.async.wait_group 0;" ::: "memory");
        }
        __syncthreads();

        const uint32_t aBase = sA + buf * 10240u;
        const uint32_t bBase = sB + buf * 10240u;
#pragma unroll
        for (int ks = 0; ks < 2; ks++) {
            uint32_t a[4][4];
#pragma unroll
            for (int mt = 0; mt < 4; mt++) {
                uint32_t addr = aBase + (uint32_t)((aRow + mt * 16) * 40 + ks * 16 + aColH) * 2;
                asm volatile("ldmatrix.sync.aligned.m8n8.x4.shared.b16 {%0,%1,%2,%3}, [%4];"
                    : "=r"(a[mt][0]), "=r"(a[mt][1]), "=r"(a[mt][2]), "=r"(a[mt][3])
                    : "r"(addr));
            }
            uint32_t b[2][4];
#pragma unroll
            for (int p = 0; p < 2; p++) {
                uint32_t addr = bBase + (uint32_t)((bRow0 + p * 16) * 40 + ks * 16 + bColH) * 2;
                asm volatile("ldmatrix.sync.aligned.m8n8.x4.shared.b16 {%0,%1,%2,%3}, [%4];"
                    : "=r"(b[p][0]), "=r"(b[p][1]), "=r"(b[p][2]), "=r"(b[p][3])
                    : "r"(addr));
            }
#pragma unroll
            for (int mt = 0; mt < 4; mt++)
#pragma unroll
                for (int nt = 0; nt < 4; nt++) {
                    const uint32_t b0 = b[nt >> 1][(nt & 1) * 2];
                    const uint32_t b1 = b[nt >> 1][(nt & 1) * 2 + 1];
                    asm volatile(
                        "mma.sync.aligned.m16n8k16.row.col.f32.f16.f16.f32 "
                        "{%0,%1,%2,%3},{%4,%5,%6,%7},{%8,%9},{%0,%1,%2,%3};"
                        : "+f"(c[mt][nt][0]), "+f"(c[mt][nt][1]),
                          "+f"(c[mt][nt][2]), "+f"(c[mt][nt][3])
                        : "r"(a[mt][0]), "r"(a[mt][1]), "r"(a[mt][2]), "r"(a[mt][3]),
                          "r"(b0), "r"(b1));
                }
        }
        __syncthreads();
    }
#undef LOADCHUNK

    const int g = lane >> 2, t = lane & 3;
#pragma unroll
    for (int mt = 0; mt < 4; mt++) {
        int r0 = bm + wm + mt * 16 + g;
#pragma unroll
        for (int nt = 0; nt < 4; nt++) {
            int col = bn + wn + nt * 8 + 2 * t;
            *(__half2*)(C + (size_t)r0 * NTOT + col) =
                __floats2half2_rn(c[mt][nt][0], c[mt][nt][1]);
            *(__half2*)(C + (size_t)(r0 + 8) * NTOT + col) =
                __floats2half2_rn(c[mt][nt][2], c[mt][nt][3]);
        }
    }
}

// ---------------- per-warp GATv2 agg for one node (lanes hold 16 dims each) ----------------
__device__ __forceinline__ void agg_node(const __half* __restrict__ xlr, int node,
                                         const int* __restrict__ row, const int* __restrict__ csrc,
                                         const float* attr, int fb, float* res /*16*/) {
    float xrr[16], acc[16];
    const uint4* rp = (const uint4*)(xlr + (size_t)node * NTOT + 512 + fb);
#pragma unroll
    for (int q = 0; q < 2; q++) {
        uint4 v = rp[q];
        float2 f0 = __half22float2(*(__half2*)&v.x);
        float2 f1 = __half22float2(*(__half2*)&v.y);
        float2 f2 = __half22float2(*(__half2*)&v.z);
        float2 f3 = __half22float2(*(__half2*)&v.w);
        xrr[q * 8 + 0] = f0.x; xrr[q * 8 + 1] = f0.y;
        xrr[q * 8 + 2] = f1.x; xrr[q * 8 + 3] = f1.y;
        xrr[q * 8 + 4] = f2.x; xrr[q * 8 + 5] = f2.y;
        xrr[q * 8 + 6] = f3.x; xrr[q * 8 + 7] = f3.y;
    }
#pragma unroll
    for (int k = 0; k < 16; k++) acc[k] = 0.f;

    float m = -CUDART_INF_F, den = 0.f;
    int j0 = row[node], j1 = row[node + 1];
    for (int j = j0; j < j1; j++) {
        int s = csrc[j];
        float xlv[16];
        const uint4* lp = (const uint4*)(xlr + (size_t)s * NTOT + fb);
#pragma unroll
        for (int q = 0; q < 2; q++) {
            uint4 v = lp[q];
            float2 f0 = __half22float2(*(__half2*)&v.x);
            float2 f1 = __half22float2(*(__half2*)&v.y);
            float2 f2 = __half22float2(*(__half2*)&v.z);
            float2 f3 = __half22float2(*(__half2*)&v.w);
            xlv[q * 8 + 0] = f0.x; xlv[q * 8 + 1] = f0.y;
            xlv[q * 8 + 2] = f1.x; xlv[q * 8 + 3] = f1.y;
            xlv[q * 8 + 4] = f2.x; xlv[q * 8 + 5] = f2.y;
            xlv[q * 8 + 6] = f3.x; xlv[q * 8 + 7] = f3.y;
        }
        float p = 0.f;
#pragma unroll
        for (int k = 0; k < 16; k++) {
            float tt = xlv[k] + xrr[k];
            tt = (tt > 0.f) ? tt : 0.2f * tt;
            p += attr[k] * tt;
        }
        p += __shfl_xor_sync(0xffffffffu, p, 1);
        p += __shfl_xor_sync(0xffffffffu, p, 2);
        float mn = fmaxf(m, p);
        float scale = __expf(m - mn);
        float w = __expf(p - mn);
        den = den * scale + w;
#pragma unroll
        for (int k = 0; k < 16; k++) acc[k] = acc[k] * scale + w * xlv[k];
        m = mn;
    }
    float inv = 1.f / (den + 1e-16f);
#pragma unroll
    for (int k = 0; k < 16; k++) res[k] = acc[k] * inv;
}

// ---------------- fused agg + GraphNorm + ReLU for layers 1/2 (concat) ----------------
// one block = one graph (64 nodes), 1024 threads = 32 warps, 2 nodes per warp.
__global__ __launch_bounds__(1024, 1)
void fused_agg_norm_kernel(const __half* __restrict__ xlr,
                           const int* __restrict__ row, const int* __restrict__ csrc,
                           const float* __restrict__ att, const float* __restrict__ bias,
                           const float* __restrict__ gnw, const float* __restrict__ gnb,
                           const float* __restrict__ gnm, __half* __restrict__ outh) {
    extern __shared__ float stage[];   // [64][512]
    const int g = blockIdx.x;
    const int tid = threadIdx.x, lane = tid & 31, warp = tid >> 5;
    const int fb = ((lane >> 2) << 6) + ((lane & 3) << 4);

    float attr[16];
    {
        const float4* ap = (const float4*)(att + fb);
#pragma unroll
        for (int q = 0; q < 4; q++) {
            float4 a = ap[q];
            attr[q * 4 + 0] = a.x; attr[q * 4 + 1] = a.y;
            attr[q * 4 + 2] = a.z; attr[q * 4 + 3] = a.w;
        }
    }

#pragma unroll
    for (int half = 0; half < 2; half++) {
        int nl = warp + 32 * half;
        int node = g * NPG + nl;
        float res[16];
        agg_node(xlr, node, row, csrc, attr, fb, res);
        float* sp = stage + nl * DD + fb;
#pragma unroll
        for (int q = 0; q < 4; q++) {
            float4 v;
            v.x = res[q * 4 + 0] + bias[fb + q * 4 + 0];
            v.y = res[q * 4 + 1] + bias[fb + q * 4 + 1];
            v.z = res[q * 4 + 2] + bias[fb + q * 4 + 2];
            v.w = res[q * 4 + 3] + bias[fb + q * 4 + 3];
            *(float4*)(sp + q * 4) = v;
        }
    }
    __syncthreads();

    if (tid < DD) {
        const int d = tid;
        float s = 0.f, q = 0.f;
#pragma unroll 8
        for (int i = 0; i < NPG; i++) {
            float x = stage[i * DD + d];
            s += x; q += x * x;
        }
        float mean = s * (1.f / NPG);
        float msm = gnm[d] * mean;
        float v = q * (1.f / NPG) - 2.f * msm * mean + msm * msm;
        float invs = rsqrtf(v + 1e-5f);
        float ww = gnw[d], bb = gnb[d];
        __half* ob = outh + (size_t)g * NPG * DD + d;
#pragma unroll 8
        for (int i = 0; i < NPG; i++) {
            float xc = stage[i * DD + d] - msm;
            float o = fmaxf(ww * xc * invs + bb, 0.f);
            ob[(size_t)i * DD] = __float2half_rn(o);
        }
    }
}

// ---------------- fused agg + norm + pool + linear for layer 3 (concat=False) ----------------
__global__ __launch_bounds__(1024, 1)
void fused_agg_norm_pool_kernel(const __half* __restrict__ xlr,
                                const int* __restrict__ row, const int* __restrict__ csrc,
                                const float* __restrict__ att, const float* __restrict__ bias,
                                const float* __restrict__ gnw, const float* __restrict__ gnb,
                                const float* __restrict__ gnm,
                                const float* __restrict__ Wlin, const float* __restrict__ blin,
                                float* __restrict__ out) {
    __shared__ float stage[NPG * FF];   // 16 KB
    __shared__ float pool[FF];
    const int g = blockIdx.x;
    const int tid = threadIdx.x, lane = tid & 31, warp = tid >> 5;
    const int fb = ((lane >> 2) << 6) + ((lane & 3) << 4);

    float attr[16];
    {
        const float4* ap = (const float4*)(att + fb);
#pragma unroll
        for (int q = 0; q < 4; q++) {
            float4 a = ap[q];
            attr[q * 4 + 0] = a.x; attr[q * 4 + 1] = a.y;
            attr[q * 4 + 2] = a.z; attr[q * 4 + 3] = a.w;
        }
    }

#pragma unroll
    for (int half = 0; half < 2; half++) {
        int nl = warp + 32 * half;
        int node = g * NPG + nl;
        float r[16];
        agg_node(xlr, node, row, csrc, attr, fb, r);
        // head-mean: sum over head groups (xor 4,8,16), then lanes 0-3 hold dims
#pragma unroll
        for (int off = 4; off < 32; off <<= 1)
#pragma unroll
            for (int k = 0; k < 16; k++) r[k] += __shfl_xor_sync(0xffffffffu, r[k], off);
        if (lane < 4) {
            int fo = lane << 4;
#pragma unroll
            for (int k = 0; k < 16; k++)
                stage[nl * FF + fo + k] = r[k] * 0.125f + bias[fo + k];
        }
    }
    __syncthreads();

    if (tid < FF) {
        const int d = tid;
        float s = 0.f, q = 0.f;
#pragma unroll 8
        for (int i = 0; i < NPG; i++) {
            float x = stage[i * FF + d];
            s += x; q += x * x;
        }
        float mean = s * (1.f / NPG);
        float msm = gnm[d] * mean;
        float v = q * (1.f / NPG) - 2.f * msm * mean + msm * msm;
        float invs = rsqrtf(v + 1e-5f);
        float ww = gnw[d], bb = gnb[d];
        float ps = 0.f;
#pragma unroll 8
        for (int i = 0; i < NPG; i++) {
            float xc = stage[i * FF + d] - msm;
            ps += fmaxf(ww * xc * invs + bb, 0.f);
        }
        pool[d] = ps * (1.f / NPG);
    }
    __syncthreads();

    if (tid < 2) {
        float o = blin[tid];
#pragma unroll
        for (int f = 0; f < FF; f++) o += pool[f] * Wlin[f * 2 + tid];
        out[g * 2 + tid] = o;
    }
}

// ---------------- host launcher ----------------
extern "C" void kernel_launch(void* const* d_in, const int* in_sizes, int n_in,
                              void* d_out, int out_size) {
    const float* x     = (const float*)d_in[0];
    const int*   esrc  = (const int*)d_in[1];
    const int*   edst  = (const int*)d_in[2];
    const float* Wl[3]  = {(const float*)d_in[4],  (const float*)d_in[11], (const float*)d_in[18]};
    const float* Wr[3]  = {(const float*)d_in[5],  (const float*)d_in[12], (const float*)d_in[19]};
    const float* att[3] = {(const float*)d_in[6],  (const float*)d_in[13], (const float*)d_in[20]};
    const float* bia[3] = {(const float*)d_in[7],  (const float*)d_in[14], (const float*)d_in[21]};
    const float* gnw[3] = {(const float*)d_in[8],  (const float*)d_in[15], (const float*)d_in[22]};
    const float* gnb[3] = {(const float*)d_in[9],  (const float*)d_in[16], (const float*)d_in[23]};
    const float* gnm[3] = {(const float*)d_in[10], (const float*)d_in[17], (const float*)d_in[24]};
    const float* Wlin = (const float*)d_in[25];
    const float* blin = (const float*)d_in[26];
    float* out = (float*)d_out;

    int E = in_sizes[1];

    __half *XLRh, *Xh, *Bh, *Wh;
    int *cnt, *row, *fill, *csrc;
    cudaGetSymbolAddress((void**)&XLRh, g_XLRh);
    cudaGetSymbolAddress((void**)&Xh,   g_Xh);
    cudaGetSymbolAddress((void**)&Bh,   g_Bh);
    cudaGetSymbolAddress((void**)&Wh,   g_Wh);
    cudaGetSymbolAddress((void**)&cnt,  g_cnt);
    cudaGetSymbolAddress((void**)&row,  g_row);
    cudaGetSymbolAddress((void**)&fill, g_fill);
    cudaGetSymbolAddress((void**)&csrc, g_csrc);

    const int FUSED_SMEM = NPG * DD * 4;   // 128 KB
    cudaFuncSetAttribute(fused_agg_norm_kernel,
                         cudaFuncAttributeMaxDynamicSharedMemorySize, FUSED_SMEM);

    // prep
    transpose_all_kernel<<<dim3(16, 16, 6), dim3(32, 8)>>>(
        Wl[0], Wr[0], Wl[1], Wr[1], Wl[2], Wr[2], Wh);
    to_half_kernel<<<(NN * 256 / 4 + 255) / 256, 256>>>((const float4*)x, (__half2*)Xh, NN * 256 / 4);

    // CSR build
    zero_int_kernel<<<(NN + 255) / 256, 256>>>(cnt, NN);
    count_kernel<<<(E + 255) / 256, 256>>>(edst, E, cnt);
    scan_kernel<<<1, 1024>>>(cnt, row, fill);
    scatter_kernel<<<(E + 255) / 256, 256>>>(esrc, edst, E, fill, csrc);

    __half* WhL[3] = {Wh, Wh + 262144, Wh + 786432};
    dim3 ggrid(NTOT / 128, NN / 128);     // (8, 128)

    // layer 1 (K=256)
    hgemm_kernel<<<ggrid, 256>>>(256, Xh, WhL[0], XLRh);
    fused_agg_norm_kernel<<<GG, 1024, FUSED_SMEM>>>(
        XLRh, row, csrc, att[0], bia[0], gnw[0], gnb[0], gnm[0], Bh);

    // layer 2 (K=512)
    hgemm_kernel<<<ggrid, 256>>>(512, Bh, WhL[1], XLRh);
    fused_agg_norm_kernel<<<GG, 1024, FUSED_SMEM>>>(
        XLRh, row, csrc, att[1], bia[1], gnw[1], gnb[1], gnm[1], Bh);

    // layer 3 (K=512, concat=False) + pool + linear
    hgemm_kernel<<<ggrid, 256>>>(512, Bh, WhL[2], XLRh);
    fused_agg_norm_pool_kernel<<<GG, 1024>>>(
        XLRh, row, csrc, att[2], bia[2], gnw[2], gnb[2], gnm[2], Wlin, blin, out);
}

// round 10
// speedup vs baseline: 1.2613x; 1.0347x over previous
#include <cuda_runtime.h>
#include <cuda_fp16.h>
#include <math_constants.h>
#include <cstdint>

// ---------------- problem constants ----------------
#define NN 16384      // nodes
#define GG 256        // graphs
#define NPG 64        // nodes per graph
#define FF 64         // per-head features
#define DD 512        // H*F
#define NTOT 1024     // fused Wl|Wr output width
#define EMAX 147456

// ---------------- scratch ----------------
__device__ __half g_XLRh[NN * NTOT];    // fused xl|xr GEMM output (fp16)
__device__ __half g_Xh[NN * 256];       // fp16 input x
__device__ __half g_Bh[NN * DD];        // fp16 norm outputs (next GEMM input)
__device__ __half g_Wh[1310720];        // fp16 transposed weights [1024][K] x 3
__device__ int    g_cnt [NN];
__device__ int    g_row [NN + 1];
__device__ int    g_fill[NN];
__device__ int    g_csrc[EMAX];

// ---------------- helpers ----------------
__device__ __forceinline__ uint32_t smem_u32(const void* p) {
    return (uint32_t)__cvta_generic_to_shared(p);
}
__device__ __forceinline__ void cp16(uint32_t d, const void* s) {
    asm volatile("cp.async.cg.shared.global [%0], [%1], 16;" :: "r"(d), "l"(s));
}

// ---------------- prep kernels ----------------
__global__ void to_half_kernel(const float4* __restrict__ in, __half2* __restrict__ out, int n4) {
    int i = blockIdx.x * blockDim.x + threadIdx.x;
    if (i < n4) {
        float4 v = in[i];
        out[i * 2]     = __floats2half2_rn(v.x, v.y);
        out[i * 2 + 1] = __floats2half2_rn(v.z, v.w);
    }
}

__global__ void transpose_all_kernel(const float* __restrict__ W0, const float* __restrict__ W1,
                                     const float* __restrict__ W2, const float* __restrict__ W3,
                                     const float* __restrict__ W4, const float* __restrict__ W5,
                                     __half* __restrict__ Wh) {
    __shared__ float t[32][33];
    const int z = blockIdx.z;
    const int K = (z < 2) ? 256 : 512;
    const int by = blockIdx.y * 32;
    if (by >= K) return;
    const float* W;
    uint32_t off;
    switch (z) {
        case 0: W = W0; off = 0u;       break;
        case 1: W = W1; off = 131072u;  break;
        case 2: W = W2; off = 262144u;  break;
        case 3: W = W3; off = 524288u;  break;
        case 4: W = W4; off = 786432u;  break;
        default:W = W5; off = 1048576u; break;
    }
    __half* Wt = Wh + off;
    const int bx = blockIdx.x * 32;
    const int x = threadIdx.x, y = threadIdx.y;
#pragma unroll
    for (int j = 0; j < 32; j += 8) t[y + j][x] = W[(size_t)(by + y + j) * DD + bx + x];
    __syncthreads();
#pragma unroll
    for (int j = 0; j < 32; j += 8)
        Wt[(size_t)(bx + y + j) * K + by + x] = __float2half_rn(t[x][y + j]);
}

// ---------------- CSR build ----------------
__global__ void zero_int_kernel(int* p, int n) {
    int i = blockIdx.x * blockDim.x + threadIdx.x;
    if (i < n) p[i] = 0;
}
__global__ void count_kernel(const int* __restrict__ dst, int E, int* __restrict__ cnt) {
    int e = blockIdx.x * blockDim.x + threadIdx.x;
    if (e < E) atomicAdd(&cnt[dst[e]], 1);
}
__global__ void scan_kernel(const int* __restrict__ cnt, int* __restrict__ row,
                            int* __restrict__ fill) {
    __shared__ int s[1024];
    int tid = threadIdx.x;
    int base = tid * 16;
    int local[16];
    int sum = 0;
#pragma unroll
    for (int i = 0; i < 16; i++) { local[i] = sum; sum += cnt[base + i]; }
    s[tid] = sum;
    __syncthreads();
    for (int off = 1; off < 1024; off <<= 1) {
        int v = (tid >= off) ? s[tid - off] : 0;
        __syncthreads();
        s[tid] += v;
        __syncthreads();
    }
    int pre = (tid == 0) ? 0 : s[tid - 1];
#pragma unroll
    for (int i = 0; i < 16; i++) {
        int o = pre + local[i];
        row[base + i]  = o;
        fill[base + i] = o;
    }
    if (tid == 1023) row[NN] = s[1023];
}
__global__ void scatter_kernel(const int* __restrict__ src, const int* __restrict__ dst,
                               int E, int* __restrict__ fill, int* __restrict__ csrc) {
    int e = blockIdx.x * blockDim.x + threadIdx.x;
    if (e < E) {
        int p = atomicAdd(&fill[dst[e]], 1);
        csrc[p] = src[e];
    }
}

// ---------------- fp16 GEMM: C[M,1024] = A[M,K] @ W[1024,K]^T, fp16 out ----------------
// CTA tile 128x128x32, 256 threads, 8 warps (2m x 4n), warp tile 64x32,
// 3-stage cp.async ring with ONE __syncthreads per K-iter.
#define STAGE_BYTES 20480u   // (A 128x40 + B 128x40) halfs = 10240+10240
#define GEMM_SMEM   (3u * STAGE_BYTES)

__global__ __launch_bounds__(256, 2)
void hgemm_kernel(int K, const __half* __restrict__ A,
                  const __half* __restrict__ W, __half* __restrict__ C) {
    extern __shared__ __align__(16) char smem[];
    const uint32_t sb = smem_u32(smem);

    const int tid = threadIdx.x, lane = tid & 31, warp = tid >> 5;
    const int wm = (warp >> 2) << 6;
    const int wn = (warp & 3) << 5;
    const int bm = blockIdx.y << 7, bn = blockIdx.x << 7;

    const int r = tid >> 1, sc = (tid & 1) << 4;
    const __half* Ag = A + (size_t)(bm + r) * K + sc;
    const __half* Wg = W + (size_t)(bn + r) * K + sc;
    const uint32_t dA = sb + (uint32_t)(r * 40 + sc) * 2;            // A at stage base
    const uint32_t dB = sb + 10240u + (uint32_t)(r * 40 + sc) * 2;   // B at stage base + 10240

#define LOADSTAGE(s, kt) do {                                    \
        uint32_t _k = (uint32_t)(kt) << 5;                       \
        cp16(dA + (s) * STAGE_BYTES,       Ag + _k);             \
        cp16(dA + (s) * STAGE_BYTES + 16u, Ag + _k + 8);         \
        cp16(dB + (s) * STAGE_BYTES,       Wg + _k);             \
        cp16(dB + (s) * STAGE_BYTES + 16u, Wg + _k + 8);         \
        asm volatile("cp.async.commit_group;" ::: "memory");     \
    } while (0)

    float c[4][4][4] = {};

    const int aRow  = wm + (lane & 15);
    const int aColH = (lane >> 4) << 3;
    const int bRow0 = wn + ((lane >> 4) << 3) + (lane & 7);
    const int bColH = ((lane >> 3) & 1) << 3;

    LOADSTAGE(0, 0);
    LOADSTAGE(1, 1);

    const int KT = K >> 5;
    int s = 0;
    for (int kt = 0; kt < KT; kt++) {
        asm volatile("cp.async.wait_group 1;" ::: "memory");
        __syncthreads();

        if (kt + 2 < KT) {
            int sn = (s + 2 >= 3) ? s - 1 : s + 2;
            LOADSTAGE(sn, kt + 2);
        } else {
            asm volatile("cp.async.commit_group;" ::: "memory");  // keep group accounting
        }

        const uint32_t aBase = sb + s * STAGE_BYTES;
        const uint32_t bBase = aBase + 10240u;
#pragma unroll
        for (int ks = 0; ks < 2; ks++) {
            uint32_t a[4][4];
#pragma unroll
            for (int mt = 0; mt < 4; mt++) {
                uint32_t addr = aBase + (uint32_t)((aRow + mt * 16) * 40 + ks * 16 + aColH) * 2;
                asm volatile("ldmatrix.sync.aligned.m8n8.x4.shared.b16 {%0,%1,%2,%3}, [%4];"
                    : "=r"(a[mt][0]), "=r"(a[mt][1]), "=r"(a[mt][2]), "=r"(a[mt][3])
                    : "r"(addr));
            }
            uint32_t b[2][4];
#pragma unroll
            for (int p = 0; p < 2; p++) {
                uint32_t addr = bBase + (uint32_t)((bRow0 + p * 16) * 40 + ks * 16 + bColH) * 2;
                asm volatile("ldmatrix.sync.aligned.m8n8.x4.shared.b16 {%0,%1,%2,%3}, [%4];"
                    : "=r"(b[p][0]), "=r"(b[p][1]), "=r"(b[p][2]), "=r"(b[p][3])
                    : "r"(addr));
            }
#pragma unroll
            for (int mt = 0; mt < 4; mt++)
#pragma unroll
                for (int nt = 0; nt < 4; nt++) {
                    const uint32_t b0 = b[nt >> 1][(nt & 1) * 2];
                    const uint32_t b1 = b[nt >> 1][(nt & 1) * 2 + 1];
                    asm volatile(
                        "mma.sync.aligned.m16n8k16.row.col.f32.f16.f16.f32 "
                        "{%0,%1,%2,%3},{%4,%5,%6,%7},{%8,%9},{%0,%1,%2,%3};"
                        : "+f"(c[mt][nt][0]), "+f"(c[mt][nt][1]),
                          "+f"(c[mt][nt][2]), "+f"(c[mt][nt][3])
                        : "r"(a[mt][0]), "r"(a[mt][1]), "r"(a[mt][2]), "r"(a[mt][3]),
                          "r"(b0), "r"(b1));
                }
        }
        s = (s + 1 >= 3) ? 0 : s + 1;
    }
#undef LOADSTAGE

    const int g = lane >> 2, t = lane & 3;
#pragma unroll
    for (int mt = 0; mt < 4; mt++) {
        int r0 = bm + wm + mt * 16 + g;
#pragma unroll
        for (int nt = 0; nt < 4; nt++) {
            int col = bn + wn + nt * 8 + 2 * t;
            *(__half2*)(C + (size_t)r0 * NTOT + col) =
                __floats2half2_rn(c[mt][nt][0], c[mt][nt][1]);
            *(__half2*)(C + (size_t)(r0 + 8) * NTOT + col) =
                __floats2half2_rn(c[mt][nt][2], c[mt][nt][3]);
        }
    }
}

// ---------------- per-warp GATv2 agg for one node ----------------
__device__ __forceinline__ void agg_node(const __half* __restrict__ xlr, int node,
                                         const int* __restrict__ row, const int* __restrict__ csrc,
                                         const float* attr, int fb, float* res /*16*/) {
    float xrr[16], acc[16];
    const uint4* rp = (const uint4*)(xlr + (size_t)node * NTOT + 512 + fb);
#pragma unroll
    for (int q = 0; q < 2; q++) {
        uint4 v = rp[q];
        float2 f0 = __half22float2(*(__half2*)&v.x);
        float2 f1 = __half22float2(*(__half2*)&v.y);
        float2 f2 = __half22float2(*(__half2*)&v.z);
        float2 f3 = __half22float2(*(__half2*)&v.w);
        xrr[q * 8 + 0] = f0.x; xrr[q * 8 + 1] = f0.y;
        xrr[q * 8 + 2] = f1.x; xrr[q * 8 + 3] = f1.y;
        xrr[q * 8 + 4] = f2.x; xrr[q * 8 + 5] = f2.y;
        xrr[q * 8 + 6] = f3.x; xrr[q * 8 + 7] = f3.y;
    }
#pragma unroll
    for (int k = 0; k < 16; k++) acc[k] = 0.f;

    float m = -CUDART_INF_F, den = 0.f;
    int j0 = row[node], j1 = row[node + 1];
    for (int j = j0; j < j1; j++) {
        int s = csrc[j];
        float xlv[16];
        const uint4* lp = (const uint4*)(xlr + (size_t)s * NTOT + fb);
#pragma unroll
        for (int q = 0; q < 2; q++) {
            uint4 v = lp[q];
            float2 f0 = __half22float2(*(__half2*)&v.x);
            float2 f1 = __half22float2(*(__half2*)&v.y);
            float2 f2 = __half22float2(*(__half2*)&v.z);
            float2 f3 = __half22float2(*(__half2*)&v.w);
            xlv[q * 8 + 0] = f0.x; xlv[q * 8 + 1] = f0.y;
            xlv[q * 8 + 2] = f1.x; xlv[q * 8 + 3] = f1.y;
            xlv[q * 8 + 4] = f2.x; xlv[q * 8 + 5] = f2.y;
            xlv[q * 8 + 6] = f3.x; xlv[q * 8 + 7] = f3.y;
        }
        float p = 0.f;
#pragma unroll
        for (int k = 0; k < 16; k++) {
            float tt = xlv[k] + xrr[k];
            tt = (tt > 0.f) ? tt : 0.2f * tt;
            p += attr[k] * tt;
        }
        p += __shfl_xor_sync(0xffffffffu, p, 1);
        p += __shfl_xor_sync(0xffffffffu, p, 2);
        float mn = fmaxf(m, p);
        float scale = __expf(m - mn);
        float w = __expf(p - mn);
        den = den * scale + w;
#pragma unroll
        for (int k = 0; k < 16; k++) acc[k] = acc[k] * scale + w * xlv[k];
        m = mn;
    }
    float inv = 1.f / (den + 1e-16f);
#pragma unroll
    for (int k = 0; k < 16; k++) res[k] = acc[k] * inv;
}

// ---------------- fused agg + GraphNorm + ReLU (layers 1/2) ----------------
__global__ __launch_bounds__(1024, 1)
void fused_agg_norm_kernel(const __half* __restrict__ xlr,
                           const int* __restrict__ row, const int* __restrict__ csrc,
                           const float* __restrict__ att, const float* __restrict__ bias,
                           const float* __restrict__ gnw, const float* __restrict__ gnb,
                           const float* __restrict__ gnm, __half* __restrict__ outh) {
    extern __shared__ float stage[];   // [64][512]
    const int g = blockIdx.x;
    const int tid = threadIdx.x, lane = tid & 31, warp = tid >> 5;
    const int fb = ((lane >> 2) << 6) + ((lane & 3) << 4);

    float attr[16];
    {
        const float4* ap = (const float4*)(att + fb);
#pragma unroll
        for (int q = 0; q < 4; q++) {
            float4 a = ap[q];
            attr[q * 4 + 0] = a.x; attr[q * 4 + 1] = a.y;
            attr[q * 4 + 2] = a.z; attr[q * 4 + 3] = a.w;
        }
    }

#pragma unroll
    for (int half = 0; half < 2; half++) {
        int nl = warp + 32 * half;
        int node = g * NPG + nl;
        float res[16];
        agg_node(xlr, node, row, csrc, attr, fb, res);
        float* sp = stage + nl * DD + fb;
#pragma unroll
        for (int q = 0; q < 4; q++) {
            float4 v;
            v.x = res[q * 4 + 0] + bias[fb + q * 4 + 0];
            v.y = res[q * 4 + 1] + bias[fb + q * 4 + 1];
            v.z = res[q * 4 + 2] + bias[fb + q * 4 + 2];
            v.w = res[q * 4 + 3] + bias[fb + q * 4 + 3];
            *(float4*)(sp + q * 4) = v;
        }
    }
    __syncthreads();

    if (tid < DD) {
        const int d = tid;
        float s = 0.f, q = 0.f;
#pragma unroll 8
        for (int i = 0; i < NPG; i++) {
            float x = stage[i * DD + d];
            s += x; q += x * x;
        }
        float mean = s * (1.f / NPG);
        float msm = gnm[d] * mean;
        float v = q * (1.f / NPG) - 2.f * msm * mean + msm * msm;
        float invs = rsqrtf(v + 1e-5f);
        float ww = gnw[d], bb = gnb[d];
        __half* ob = outh + (size_t)g * NPG * DD + d;
#pragma unroll 8
        for (int i = 0; i < NPG; i++) {
            float xc = stage[i * DD + d] - msm;
            float o = fmaxf(ww * xc * invs + bb, 0.f);
            ob[(size_t)i * DD] = __float2half_rn(o);
        }
    }
}

// ---------------- fused agg + norm + pool + linear (layer 3) ----------------
__global__ __launch_bounds__(1024, 1)
void fused_agg_norm_pool_kernel(const __half* __restrict__ xlr,
                                const int* __restrict__ row, const int* __restrict__ csrc,
                                const float* __restrict__ att, const float* __restrict__ bias,
                                const float* __restrict__ gnw, const float* __restrict__ gnb,
                                const float* __restrict__ gnm,
                                const float* __restrict__ Wlin, const float* __restrict__ blin,
                                float* __restrict__ out) {
    __shared__ float stage[NPG * FF];
    __shared__ float pool[FF];
    const int g = blockIdx.x;
    const int tid = threadIdx.x, lane = tid & 31, warp = tid >> 5;
    const int fb = ((lane >> 2) << 6) + ((lane & 3) << 4);

    float attr[16];
    {
        const float4* ap = (const float4*)(att + fb);
#pragma unroll
        for (int q = 0; q < 4; q++) {
            float4 a = ap[q];
            attr[q * 4 + 0] = a.x; attr[q * 4 + 1] = a.y;
            attr[q * 4 + 2] = a.z; attr[q * 4 + 3] = a.w;
        }
    }

#pragma unroll
    for (int half = 0; half < 2; half++) {
        int nl = warp + 32 * half;
        int node = g * NPG + nl;
        float r[16];
        agg_node(xlr, node, row, csrc, attr, fb, r);
#pragma unroll
        for (int off = 4; off < 32; off <<= 1)
#pragma unroll
            for (int k = 0; k < 16; k++) r[k] += __shfl_xor_sync(0xffffffffu, r[k], off);
        if (lane < 4) {
            int fo = lane << 4;
#pragma unroll
            for (int k = 0; k < 16; k++)
                stage[nl * FF + fo + k] = r[k] * 0.125f + bias[fo + k];
        }
    }
    __syncthreads();

    if (tid < FF) {
        const int d = tid;
        float s = 0.f, q = 0.f;
#pragma unroll 8
        for (int i = 0; i < NPG; i++) {
            float x = stage[i * FF + d];
            s += x; q += x * x;
        }
        float mean = s * (1.f / NPG);
        float msm = gnm[d] * mean;
        float v = q * (1.f / NPG) - 2.f * msm * mean + msm * msm;
        float invs = rsqrtf(v + 1e-5f);
        float ww = gnw[d], bb = gnb[d];
        float ps = 0.f;
#pragma unroll 8
        for (int i = 0; i < NPG; i++) {
            float xc = stage[i * FF + d] - msm;
            ps += fmaxf(ww * xc * invs + bb, 0.f);
        }
        pool[d] = ps * (1.f / NPG);
    }
    __syncthreads();

    if (tid < 2) {
        float o = blin[tid];
#pragma unroll
        for (int f = 0; f < FF; f++) o += pool[f] * Wlin[f * 2 + tid];
        out[g * 2 + tid] = o;
    }
}

// ---------------- host launcher ----------------
extern "C" void kernel_launch(void* const* d_in, const int* in_sizes, int n_in,
                              void* d_out, int out_size) {
    const float* x     = (const float*)d_in[0];
    const int*   esrc  = (const int*)d_in[1];
    const int*   edst  = (const int*)d_in[2];
    const float* Wl[3]  = {(const float*)d_in[4],  (const float*)d_in[11], (const float*)d_in[18]};
    const float* Wr[3]  = {(const float*)d_in[5],  (const float*)d_in[12], (const float*)d_in[19]};
    const float* att[3] = {(const float*)d_in[6],  (const float*)d_in[13], (const float*)d_in[20]};
    const float* bia[3] = {(const float*)d_in[7],  (const float*)d_in[14], (const float*)d_in[21]};
    const float* gnw[3] = {(const float*)d_in[8],  (const float*)d_in[15], (const float*)d_in[22]};
    const float* gnb[3] = {(const float*)d_in[9],  (const float*)d_in[16], (const float*)d_in[23]};
    const float* gnm[3] = {(const float*)d_in[10], (const float*)d_in[17], (const float*)d_in[24]};
    const float* Wlin = (const float*)d_in[25];
    const float* blin = (const float*)d_in[26];
    float* out = (float*)d_out;

    int E = in_sizes[1];

    __half *XLRh, *Xh, *Bh, *Wh;
    int *cnt, *row, *fill, *csrc;
    cudaGetSymbolAddress((void**)&XLRh, g_XLRh);
    cudaGetSymbolAddress((void**)&Xh,   g_Xh);
    cudaGetSymbolAddress((void**)&Bh,   g_Bh);
    cudaGetSymbolAddress((void**)&Wh,   g_Wh);
    cudaGetSymbolAddress((void**)&cnt,  g_cnt);
    cudaGetSymbolAddress((void**)&row,  g_row);
    cudaGetSymbolAddress((void**)&fill, g_fill);
    cudaGetSymbolAddress((void**)&csrc, g_csrc);

    const int FUSED_SMEM = NPG * DD * 4;   // 128 KB
    cudaFuncSetAttribute(fused_agg_norm_kernel,
                         cudaFuncAttributeMaxDynamicSharedMemorySize, FUSED_SMEM);
    cudaFuncSetAttribute(hgemm_kernel,
                         cudaFuncAttributeMaxDynamicSharedMemorySize, GEMM_SMEM);

    // prep
    transpose_all_kernel<<<dim3(16, 16, 6), dim3(32, 8)>>>(
        Wl[0], Wr[0], Wl[1], Wr[1], Wl[2], Wr[2], Wh);
    to_half_kernel<<<(NN * 256 / 4 + 255) / 256, 256>>>((const float4*)x, (__half2*)Xh, NN * 256 / 4);

    // CSR build
    zero_int_kernel<<<(NN + 255) / 256, 256>>>(cnt, NN);
    count_kernel<<<(E + 255) / 256, 256>>>(edst, E, cnt);
    scan_kernel<<<1, 1024>>>(cnt, row, fill);
    scatter_kernel<<<(E + 255) / 256, 256>>>(esrc, edst, E, fill, csrc);

    __half* WhL[3] = {Wh, Wh + 262144, Wh + 786432};
    dim3 ggrid(NTOT / 128, NN / 128);     // (8, 128)

    // layer 1 (K=256)
    hgemm_kernel<<<ggrid, 256, GEMM_SMEM>>>(256, Xh, WhL[0], XLRh);
    fused_agg_norm_kernel<<<GG, 1024, FUSED_SMEM>>>(
        XLRh, row, csrc, att[0], bia[0], gnw[0], gnb[0], gnm[0], Bh);

    // layer 2 (K=512)
    hgemm_kernel<<<ggrid, 256, GEMM_SMEM>>>(512, Bh, WhL[1], XLRh);
    fused_agg_norm_kernel<<<GG, 1024, FUSED_SMEM>>>(
        XLRh, row, csrc, att[1], bia[1], gnw[1], gnb[1], gnm[1], Bh);

    // layer 3 (K=512, concat=False) + pool + linear
    hgemm_kernel<<<ggrid, 256, GEMM_SMEM>>>(512, Bh, WhL[2], XLRh);
    fused_agg_norm_pool_kernel<<<GG, 1024>>>(
        XLRh, row, csrc, att[2], bia[2], gnw[2], gnb[2], gnm[2], Wlin, blin, out);
}

// round 11
// speedup vs baseline: 1.5335x; 1.2158x over previous
#include <cuda_runtime.h>
#include <cuda_fp16.h>
#include <math_constants.h>
#include <cstdint>

// ---------------- problem constants ----------------
#define NN 16384      // nodes
#define GG 256        // graphs
#define NPG 64        // nodes per graph
#define FF 64         // per-head features
#define DD 512        // H*F
#define NTOT 1024     // fused Wl|Wr output width
#define EMAX 147456

// ---------------- scratch ----------------
__device__ __half g_XLRh[NN * NTOT];    // fused xl|xr GEMM output (fp16)
__device__ __half g_Xh[NN * 256];       // fp16 input x
__device__ __half g_Bh[NN * DD];        // fp16 norm outputs (next GEMM input)
__device__ __half g_Wh[1310720];        // fp16 transposed weights [1024][K] x 3
__device__ int    g_cnt [NN];
__device__ int    g_row [NN + 1];
__device__ int    g_fill[NN];
__device__ int    g_csrc[EMAX];

// ---------------- helpers ----------------
__device__ __forceinline__ uint32_t smem_u32(const void* p) {
    return (uint32_t)__cvta_generic_to_shared(p);
}
__device__ __forceinline__ void cp16(uint32_t d, const void* s) {
    asm volatile("cp.async.cg.shared.global [%0], [%1], 16;" :: "r"(d), "l"(s));
}

// ---------------- prep kernels ----------------
__global__ void to_half_kernel(const float4* __restrict__ in, __half2* __restrict__ out, int n4) {
    int i = blockIdx.x * blockDim.x + threadIdx.x;
    if (i < n4) {
        float4 v = in[i];
        out[i * 2]     = __floats2half2_rn(v.x, v.y);
        out[i * 2 + 1] = __floats2half2_rn(v.z, v.w);
    }
}

__global__ void transpose_all_kernel(const float* __restrict__ W0, const float* __restrict__ W1,
                                     const float* __restrict__ W2, const float* __restrict__ W3,
                                     const float* __restrict__ W4, const float* __restrict__ W5,
                                     __half* __restrict__ Wh) {
    __shared__ float t[32][33];
    const int z = blockIdx.z;
    const int K = (z < 2) ? 256 : 512;
    const int by = blockIdx.y * 32;
    if (by >= K) return;
    const float* W;
    uint32_t off;
    switch (z) {
        case 0: W = W0; off = 0u;       break;
        case 1: W = W1; off = 131072u;  break;
        case 2: W = W2; off = 262144u;  break;
        case 3: W = W3; off = 524288u;  break;
        case 4: W = W4; off = 786432u;  break;
        default:W = W5; off = 1048576u; break;
    }
    __half* Wt = Wh + off;
    const int bx = blockIdx.x * 32;
    const int x = threadIdx.x, y = threadIdx.y;
#pragma unroll
    for (int j = 0; j < 32; j += 8) t[y + j][x] = W[(size_t)(by + y + j) * DD + bx + x];
    __syncthreads();
#pragma unroll
    for (int j = 0; j < 32; j += 8)
        Wt[(size_t)(bx + y + j) * K + by + x] = __float2half_rn(t[x][y + j]);
}

// ---------------- CSR build ----------------
__global__ void zero_int_kernel(int* p, int n) {
    int i = blockIdx.x * blockDim.x + threadIdx.x;
    if (i < n) p[i] = 0;
}
__global__ void count_kernel(const int* __restrict__ dst, int E, int* __restrict__ cnt) {
    int e = blockIdx.x * blockDim.x + threadIdx.x;
    if (e < E) atomicAdd(&cnt[dst[e]], 1);
}
__global__ void scan_kernel(const int* __restrict__ cnt, int* __restrict__ row,
                            int* __restrict__ fill) {
    __shared__ int s[1024];
    int tid = threadIdx.x;
    int base = tid * 16;
    int local[16];
    int sum = 0;
#pragma unroll
    for (int i = 0; i < 16; i++) { local[i] = sum; sum += cnt[base + i]; }
    s[tid] = sum;
    __syncthreads();
    for (int off = 1; off < 1024; off <<= 1) {
        int v = (tid >= off) ? s[tid - off] : 0;
        __syncthreads();
        s[tid] += v;
        __syncthreads();
    }
    int pre = (tid == 0) ? 0 : s[tid - 1];
#pragma unroll
    for (int i = 0; i < 16; i++) {
        int o = pre + local[i];
        row[base + i]  = o;
        fill[base + i] = o;
    }
    if (tid == 1023) row[NN] = s[1023];
}
__global__ void scatter_kernel(const int* __restrict__ src, const int* __restrict__ dst,
                               int E, int* __restrict__ fill, int* __restrict__ csrc) {
    int e = blockIdx.x * blockDim.x + threadIdx.x;
    if (e < E) {
        int p = atomicAdd(&fill[dst[e]], 1);
        csrc[p] = src[e];
    }
}

// ---------------- fp16 GEMM: C[M,1024] = A[M,K] @ W[1024,K]^T, fp16 out ----------------
// CTA tile 128x128x32, 256 threads, 8 warps (2m x 4n), warp tile 64x32,
// 3-stage cp.async ring with ONE __syncthreads per K-iter.
#define STAGE_BYTES 20480u
#define GEMM_SMEM   (3u * STAGE_BYTES)

__global__ __launch_bounds__(256, 2)
void hgemm_kernel(int K, const __half* __restrict__ A,
                  const __half* __restrict__ W, __half* __restrict__ C) {
    extern __shared__ __align__(16) char smem[];
    const uint32_t sb = smem_u32(smem);

    const int tid = threadIdx.x, lane = tid & 31, warp = tid >> 5;
    const int wm = (warp >> 2) << 6;
    const int wn = (warp & 3) << 5;
    const int bm = blockIdx.y << 7, bn = blockIdx.x << 7;

    const int r = tid >> 1, sc = (tid & 1) << 4;
    const __half* Ag = A + (size_t)(bm + r) * K + sc;
    const __half* Wg = W + (size_t)(bn + r) * K + sc;
    const uint32_t dA = sb + (uint32_t)(r * 40 + sc) * 2;
    const uint32_t dB = sb + 10240u + (uint32_t)(r * 40 + sc) * 2;

#define LOADSTAGE(s, kt) do {                                    \
        uint32_t _k = (uint32_t)(kt) << 5;                       \
        cp16(dA + (s) * STAGE_BYTES,       Ag + _k);             \
        cp16(dA + (s) * STAGE_BYTES + 16u, Ag + _k + 8);         \
        cp16(dB + (s) * STAGE_BYTES,       Wg + _k);             \
        cp16(dB + (s) * STAGE_BYTES + 16u, Wg + _k + 8);         \
        asm volatile("cp.async.commit_group;" ::: "memory");     \
    } while (0)

    float c[4][4][4] = {};

    const int aRow  = wm + (lane & 15);
    const int aColH = (lane >> 4) << 3;
    const int bRow0 = wn + ((lane >> 4) << 3) + (lane & 7);
    const int bColH = ((lane >> 3) & 1) << 3;

    LOADSTAGE(0, 0);
    LOADSTAGE(1, 1);

    const int KT = K >> 5;
    int s = 0;
    for (int kt = 0; kt < KT; kt++) {
        asm volatile("cp.async.wait_group 1;" ::: "memory");
        __syncthreads();

        if (kt + 2 < KT) {
            int sn = (s + 2 >= 3) ? s - 1 : s + 2;
            LOADSTAGE(sn, kt + 2);
        } else {
            asm volatile("cp.async.commit_group;" ::: "memory");
        }

        const uint32_t aBase = sb + s * STAGE_BYTES;
        const uint32_t bBase = aBase + 10240u;
#pragma unroll
        for (int ks = 0; ks < 2; ks++) {
            uint32_t a[4][4];
#pragma unroll
            for (int mt = 0; mt < 4; mt++) {
                uint32_t addr = aBase + (uint32_t)((aRow + mt * 16) * 40 + ks * 16 + aColH) * 2;
                asm volatile("ldmatrix.sync.aligned.m8n8.x4.shared.b16 {%0,%1,%2,%3}, [%4];"
                    : "=r"(a[mt][0]), "=r"(a[mt][1]), "=r"(a[mt][2]), "=r"(a[mt][3])
                    : "r"(addr));
            }
            uint32_t b[2][4];
#pragma unroll
            for (int p = 0; p < 2; p++) {
                uint32_t addr = bBase + (uint32_t)((bRow0 + p * 16) * 40 + ks * 16 + bColH) * 2;
                asm volatile("ldmatrix.sync.aligned.m8n8.x4.shared.b16 {%0,%1,%2,%3}, [%4];"
                    : "=r"(b[p][0]), "=r"(b[p][1]), "=r"(b[p][2]), "=r"(b[p][3])
                    : "r"(addr));
            }
#pragma unroll
            for (int mt = 0; mt < 4; mt++)
#pragma unroll
                for (int nt = 0; nt < 4; nt++) {
                    const uint32_t b0 = b[nt >> 1][(nt & 1) * 2];
                    const uint32_t b1 = b[nt >> 1][(nt & 1) * 2 + 1];
                    asm volatile(
                        "mma.sync.aligned.m16n8k16.row.col.f32.f16.f16.f32 "
                        "{%0,%1,%2,%3},{%4,%5,%6,%7},{%8,%9},{%0,%1,%2,%3};"
                        : "+f"(c[mt][nt][0]), "+f"(c[mt][nt][1]),
                          "+f"(c[mt][nt][2]), "+f"(c[mt][nt][3])
                        : "r"(a[mt][0]), "r"(a[mt][1]), "r"(a[mt][2]), "r"(a[mt][3]),
                          "r"(b0), "r"(b1));
                }
        }
        s = (s + 1 >= 3) ? 0 : s + 1;
    }
#undef LOADSTAGE

    const int g = lane >> 2, t = lane & 3;
#pragma unroll
    for (int mt = 0; mt < 4; mt++) {
        int r0 = bm + wm + mt * 16 + g;
#pragma unroll
        for (int nt = 0; nt < 4; nt++) {
            int col = bn + wn + nt * 8 + 2 * t;
            *(__half2*)(C + (size_t)r0 * NTOT + col) =
                __floats2half2_rn(c[mt][nt][0], c[mt][nt][1]);
            *(__half2*)(C + (size_t)(r0 + 8) * NTOT + col) =
                __floats2half2_rn(c[mt][nt][2], c[mt][nt][3]);
        }
    }
}

// ---------------- per-warp GATv2 agg for one node (half2 logit path) ----------------
__device__ __forceinline__ void agg_node(const __half* __restrict__ xlr, int node,
                                         const int* __restrict__ row, const int* __restrict__ csrc,
                                         const __half2* att2 /*8*/, int fb, float* res /*16*/) {
    __half2 xr2[8];
    {
        const uint4* rp = (const uint4*)(xlr + (size_t)node * NTOT + 512 + fb);
#pragma unroll
        for (int q = 0; q < 2; q++) {
            uint4 v = rp[q];
            xr2[q * 4 + 0] = *(__half2*)&v.x;
            xr2[q * 4 + 1] = *(__half2*)&v.y;
            xr2[q * 4 + 2] = *(__half2*)&v.z;
            xr2[q * 4 + 3] = *(__half2*)&v.w;
        }
    }
    float acc[16];
#pragma unroll
    for (int k = 0; k < 16; k++) acc[k] = 0.f;

    const __half2 c02 = __float2half2_rn(0.2f);
    float m = -CUDART_INF_F, den = 0.f;
    int j0 = row[node], j1 = row[node + 1];
    for (int j = j0; j < j1; j++) {
        int s = csrc[j];
        __half2 xl2[8];
        const uint4* lp = (const uint4*)(xlr + (size_t)s * NTOT + fb);
#pragma unroll
        for (int q = 0; q < 2; q++) {
            uint4 v = lp[q];
            xl2[q * 4 + 0] = *(__half2*)&v.x;
            xl2[q * 4 + 1] = *(__half2*)&v.y;
            xl2[q * 4 + 2] = *(__half2*)&v.z;
            xl2[q * 4 + 3] = *(__half2*)&v.w;
        }
        // logit: att . leaky(xl + xr), leaky(t) = max(t, 0.2t)
        __half2 dot = __float2half2_rn(0.f);
#pragma unroll
        for (int q = 0; q < 8; q++) {
            __half2 t = __hadd2(xl2[q], xr2[q]);
            __half2 l = __hmax2(t, __hmul2(t, c02));
            dot = __hfma2(att2[q], l, dot);
        }
        float2 d2 = __half22float2(dot);
        float p = d2.x + d2.y;
        p += __shfl_xor_sync(0xffffffffu, p, 1);
        p += __shfl_xor_sync(0xffffffffu, p, 2);
        float mn = fmaxf(m, p);
        float scale = __expf(m - mn);
        float w = __expf(p - mn);
        den = den * scale + w;
#pragma unroll
        for (int q = 0; q < 8; q++) {
            float2 f = __half22float2(xl2[q]);
            acc[q * 2 + 0] = acc[q * 2 + 0] * scale + w * f.x;
            acc[q * 2 + 1] = acc[q * 2 + 1] * scale + w * f.y;
        }
        m = mn;
    }
    float inv = 1.f / (den + 1e-16f);
#pragma unroll
    for (int k = 0; k < 16; k++) res[k] = acc[k] * inv;
}

// ---------------- fused agg + GraphNorm + ReLU (layers 1/2) ----------------
__global__ __launch_bounds__(1024, 1)
void fused_agg_norm_kernel(const __half* __restrict__ xlr,
                           const int* __restrict__ row, const int* __restrict__ csrc,
                           const float* __restrict__ att, const float* __restrict__ bias,
                           const float* __restrict__ gnw, const float* __restrict__ gnb,
                           const float* __restrict__ gnm, __half* __restrict__ outh) {
    extern __shared__ float stage[];   // [64][512]
    const int g = blockIdx.x;
    const int tid = threadIdx.x, lane = tid & 31, warp = tid >> 5;
    const int fb = ((lane >> 2) << 6) + ((lane & 3) << 4);

    __half2 att2[8];
    {
        const float4* ap = (const float4*)(att + fb);
#pragma unroll
        for (int q = 0; q < 4; q++) {
            float4 a = ap[q];
            att2[q * 2 + 0] = __floats2half2_rn(a.x, a.y);
            att2[q * 2 + 1] = __floats2half2_rn(a.z, a.w);
        }
    }

#pragma unroll
    for (int half = 0; half < 2; half++) {
        int nl = warp + 32 * half;
        int node = g * NPG + nl;
        float res[16];
        agg_node(xlr, node, row, csrc, att2, fb, res);
        float* sp = stage + nl * DD + fb;
#pragma unroll
        for (int q = 0; q < 4; q++) {
            float4 v;
            v.x = res[q * 4 + 0] + bias[fb + q * 4 + 0];
            v.y = res[q * 4 + 1] + bias[fb + q * 4 + 1];
            v.z = res[q * 4 + 2] + bias[fb + q * 4 + 2];
            v.w = res[q * 4 + 3] + bias[fb + q * 4 + 3];
            *(float4*)(sp + q * 4) = v;
        }
    }
    __syncthreads();

    if (tid < DD) {
        const int d = tid;
        float s = 0.f, q = 0.f;
#pragma unroll 8
        for (int i = 0; i < NPG; i++) {
            float x = stage[i * DD + d];
            s += x; q += x * x;
        }
        float mean = s * (1.f / NPG);
        float msm = gnm[d] * mean;
        float v = q * (1.f / NPG) - 2.f * msm * mean + msm * msm;
        float invs = rsqrtf(v + 1e-5f);
        float ww = gnw[d], bb = gnb[d];
        __half* ob = outh + (size_t)g * NPG * DD + d;
#pragma unroll 8
        for (int i = 0; i < NPG; i++) {
            float xc = stage[i * DD + d] - msm;
            float o = fmaxf(ww * xc * invs + bb, 0.f);
            ob[(size_t)i * DD] = __float2half_rn(o);
        }
    }
}

// ---------------- fused agg + norm + pool + linear (layer 3) ----------------
__global__ __launch_bounds__(1024, 1)
void fused_agg_norm_pool_kernel(const __half* __restrict__ xlr,
                                const int* __restrict__ row, const int* __restrict__ csrc,
                                const float* __restrict__ att, const float* __restrict__ bias,
                                const float* __restrict__ gnw, const float* __restrict__ gnb,
                                const float* __restrict__ gnm,
                                const float* __restrict__ Wlin, const float* __restrict__ blin,
                                float* __restrict__ out) {
    __shared__ float stage[NPG * FF];
    __shared__ float pool[FF];
    const int g = blockIdx.x;
    const int tid = threadIdx.x, lane = tid & 31, warp = tid >> 5;
    const int fb = ((lane >> 2) << 6) + ((lane & 3) << 4);

    __half2 att2[8];
    {
        const float4* ap = (const float4*)(att + fb);
#pragma unroll
        for (int q = 0; q < 4; q++) {
            float4 a = ap[q];
            att2[q * 2 + 0] = __floats2half2_rn(a.x, a.y);
            att2[q * 2 + 1] = __floats2half2_rn(a.z, a.w);
        }
    }

#pragma unroll
    for (int half = 0; half < 2; half++) {
        int nl = warp + 32 * half;
        int node = g * NPG + nl;
        float r[16];
        agg_node(xlr, node, row, csrc, att2, fb, r);
#pragma unroll
        for (int off = 4; off < 32; off <<= 1)
#pragma unroll
            for (int k = 0; k < 16; k++) r[k] += __shfl_xor_sync(0xffffffffu, r[k], off);
        if (lane < 4) {
            int fo = lane << 4;
#pragma unroll
            for (int k = 0; k < 16; k++)
                stage[nl * FF + fo + k] = r[k] * 0.125f + bias[fo + k];
        }
    }
    __syncthreads();

    if (tid < FF) {
        const int d = tid;
        float s = 0.f, q = 0.f;
#pragma unroll 8
        for (int i = 0; i < NPG; i++) {
            float x = stage[i * FF + d];
            s += x; q += x * x;
        }
        float mean = s * (1.f / NPG);
        float msm = gnm[d] * mean;
        float v = q * (1.f / NPG) - 2.f * msm * mean + msm * msm;
        float invs = rsqrtf(v + 1e-5f);
        float ww = gnw[d], bb = gnb[d];
        float ps = 0.f;
#pragma unroll 8
        for (int i = 0; i < NPG; i++) {
            float xc = stage[i * FF + d] - msm;
            ps += fmaxf(ww * xc * invs + bb, 0.f);
        }
        pool[d] = ps * (1.f / NPG);
    }
    __syncthreads();

    if (tid < 2) {
        float o = blin[tid];
#pragma unroll
        for (int f = 0; f < FF; f++) o += pool[f] * Wlin[f * 2 + tid];
        out[g * 2 + tid] = o;
    }
}

// ---------------- host launcher ----------------
extern "C" void kernel_launch(void* const* d_in, const int* in_sizes, int n_in,
                              void* d_out, int out_size) {
    const float* x     = (const float*)d_in[0];
    const int*   esrc  = (const int*)d_in[1];
    const int*   edst  = (const int*)d_in[2];
    const float* Wl[3]  = {(const float*)d_in[4],  (const float*)d_in[11], (const float*)d_in[18]};
    const float* Wr[3]  = {(const float*)d_in[5],  (const float*)d_in[12], (const float*)d_in[19]};
    const float* att[3] = {(const float*)d_in[6],  (const float*)d_in[13], (const float*)d_in[20]};
    const float* bia[3] = {(const float*)d_in[7],  (const float*)d_in[14], (const float*)d_in[21]};
    const float* gnw[3] = {(const float*)d_in[8],  (const float*)d_in[15], (const float*)d_in[22]};
    const float* gnb[3] = {(const float*)d_in[9],  (const float*)d_in[16], (const float*)d_in[23]};
    const float* gnm[3] = {(const float*)d_in[10], (const float*)d_in[17], (const float*)d_in[24]};
    const float* Wlin = (const float*)d_in[25];
    const float* blin = (const float*)d_in[26];
    float* out = (float*)d_out;

    int E = in_sizes[1];

    __half *XLRh, *Xh, *Bh, *Wh;
    int *cnt, *row, *fill, *csrc;
    cudaGetSymbolAddress((void**)&XLRh, g_XLRh);
    cudaGetSymbolAddress((void**)&Xh,   g_Xh);
    cudaGetSymbolAddress((void**)&Bh,   g_Bh);
    cudaGetSymbolAddress((void**)&Wh,   g_Wh);
    cudaGetSymbolAddress((void**)&cnt,  g_cnt);
    cudaGetSymbolAddress((void**)&row,  g_row);
    cudaGetSymbolAddress((void**)&fill, g_fill);
    cudaGetSymbolAddress((void**)&csrc, g_csrc);

    const int FUSED_SMEM = NPG * DD * 4;   // 128 KB
    cudaFuncSetAttribute(fused_agg_norm_kernel,
                         cudaFuncAttributeMaxDynamicSharedMemorySize, FUSED_SMEM);
    cudaFuncSetAttribute(hgemm_kernel,
                         cudaFuncAttributeMaxDynamicSharedMemorySize, GEMM_SMEM);

    // ---- fork CSR build onto a side stream (capture-legal event fork/join) ----
    cudaStream_t s2;
    cudaStreamCreateWithFlags(&s2, cudaStreamNonBlocking);
    cudaEvent_t e1, e2;
    cudaEventCreateWithFlags(&e1, cudaEventDisableTiming);
    cudaEventCreateWithFlags(&e2, cudaEventDisableTiming);

    cudaEventRecord(e1, 0);
    cudaStreamWaitEvent(s2, e1, 0);
    zero_int_kernel<<<(NN + 255) / 256, 256, 0, s2>>>(cnt, NN);
    count_kernel<<<(E + 255) / 256, 256, 0, s2>>>(edst, E, cnt);
    scan_kernel<<<1, 1024, 0, s2>>>(cnt, row, fill);
    scatter_kernel<<<(E + 255) / 256, 256, 0, s2>>>(esrc, edst, E, fill, csrc);
    cudaEventRecord(e2, s2);

    // ---- main stream: prep + layer 1 GEMM (independent of CSR) ----
    transpose_all_kernel<<<dim3(16, 16, 6), dim3(32, 8)>>>(
        Wl[0], Wr[0], Wl[1], Wr[1], Wl[2], Wr[2], Wh);
    to_half_kernel<<<(NN * 256 / 4 + 255) / 256, 256>>>((const float4*)x, (__half2*)Xh, NN * 256 / 4);

    __half* WhL[3] = {Wh, Wh + 262144, Wh + 786432};
    dim3 ggrid(NTOT / 128, NN / 128);     // (8, 128)

    hgemm_kernel<<<ggrid, 256, GEMM_SMEM>>>(256, Xh, WhL[0], XLRh);

    // join: agg needs the CSR
    cudaStreamWaitEvent(0, e2, 0);

    fused_agg_norm_kernel<<<GG, 1024, FUSED_SMEM>>>(
        XLRh, row, csrc, att[0], bia[0], gnw[0], gnb[0], gnm[0], Bh);

    // layer 2 (K=512)
    hgemm_kernel<<<ggrid, 256, GEMM_SMEM>>>(512, Bh, WhL[1], XLRh);
    fused_agg_norm_kernel<<<GG, 1024, FUSED_SMEM>>>(
        XLRh, row, csrc, att[1], bia[1], gnw[1], gnb[1], gnm[1], Bh);

    // layer 3 (K=512, concat=False) + pool + linear
    hgemm_kernel<<<ggrid, 256, GEMM_SMEM>>>(512, Bh, WhL[2], XLRh);
    fused_agg_norm_pool_kernel<<<GG, 1024>>>(
        XLRh, row, csrc, att[2], bia[2], gnw[2], gnb[2], gnm[2], Wlin, blin, out);

    cudaEventDestroy(e1);
    cudaEventDestroy(e2);
    cudaStreamDestroy(s2);
}